// round 3
// baseline (speedup 1.0000x reference)
#include <cuda_runtime.h>
#include <cuda_bf16.h>

#define Bb 8
#define Hh 9
#define Ee 128
#define Ss 1025
#define HE 1152     // Hh*Ee
#define VTS 1026    // padded row stride for transposed V (even => aligned float2)
#define TPITCH 136  // bf16 tile row pitch (elements); 272B, 16B-aligned, ldmatrix conflict-free
#define TSZ (128 * TPITCH)   // elements per 128x128 tile

typedef unsigned long long ull;
typedef unsigned int u32;

// ---------------- scratch (no allocations allowed) ----------------
__device__ float g_q[Bb * Hh * Ss * Ee];
__device__ float g_k[Bb * Hh * Ss * Ee];
__device__ float g_vt[(size_t)Bb * Hh * Ee * VTS];   // V transposed: [bh][f][t]
__device__ float g_ho[Bb * Ss * HE];                 // head outputs [b][s][h*E+f]

// ---------------- f32x2 helpers (fp32 kernels) ----------------
__device__ __forceinline__ ull fdup(float v) {
    unsigned u = __float_as_uint(v);
    return ((ull)u << 32) | (ull)u;
}
__device__ __forceinline__ void ffma2(ull& d, ull a, ull b) {
    asm("fma.rn.f32x2 %0, %1, %2, %0;" : "+l"(d) : "l"(a), "l"(b));
}
__device__ __forceinline__ float f2lo(ull v) { return __uint_as_float((unsigned)v); }
__device__ __forceinline__ float f2hi(ull v) { return __uint_as_float((unsigned)(v >> 32)); }

// ---------------- mma.sync helpers ----------------
__device__ __forceinline__ u32 s2u(const void* p) {
    u32 a;
    asm("{ .reg .u64 t; cvta.to.shared.u64 t, %1; cvt.u32.u64 %0, t; }" : "=r"(a) : "l"(p));
    return a;
}
__device__ __forceinline__ void ldmx4(u32& a0, u32& a1, u32& a2, u32& a3, u32 addr) {
    asm volatile("ldmatrix.sync.aligned.m8n8.x4.shared.b16 {%0,%1,%2,%3}, [%4];"
                 : "=r"(a0), "=r"(a1), "=r"(a2), "=r"(a3) : "r"(addr));
}
__device__ __forceinline__ void ldmx2(u32& b0, u32& b1, u32 addr) {
    asm volatile("ldmatrix.sync.aligned.m8n8.x2.shared.b16 {%0,%1}, [%2];"
                 : "=r"(b0), "=r"(b1) : "r"(addr));
}
__device__ __forceinline__ void mma16816(float* c, u32 a0, u32 a1, u32 a2, u32 a3,
                                         u32 b0, u32 b1) {
    asm volatile("mma.sync.aligned.m16n8k16.row.col.f32.bf16.bf16.f32 "
                 "{%0,%1,%2,%3}, {%4,%5,%6,%7}, {%8,%9}, {%0,%1,%2,%3};"
                 : "+f"(c[0]), "+f"(c[1]), "+f"(c[2]), "+f"(c[3])
                 : "r"(a0), "r"(a1), "r"(a2), "r"(a3), "r"(b0), "r"(b1));
}

__device__ __forceinline__ void split3(float x, __nv_bfloat16& a, __nv_bfloat16& b, __nv_bfloat16& c) {
    a = __float2bfloat16(x); float r = x - __bfloat162float(a);
    b = __float2bfloat16(r); float r2 = r - __bfloat162float(b);
    c = __float2bfloat16(r2);
}
__device__ __forceinline__ void split2(float x, __nv_bfloat16& a, __nv_bfloat16& b) {
    a = __float2bfloat16(x); float r = x - __bfloat162float(a);
    b = __float2bfloat16(r);
}

// =================================================================
// Kernel 1: projections (fp32 f32x2). z=0->q, z=1->k, z=2->v (transposed)
// =================================================================
__global__ __launch_bounds__(256) void proj_kernel(
    const float* __restrict__ x, const float* __restrict__ Qw,
    const float* __restrict__ Kw, const float* __restrict__ Vw)
{
    extern __shared__ unsigned char sm1[];
    ull*   xsd = (ull*)sm1;                      // [64][129] duplicated pairs
    float* ws  = (float*)(sm1 + 64 * 129 * 8);   // [128][132]

    const int tid = threadIdx.x;
    const int s0  = blockIdx.x * 64;
    const int bh  = blockIdx.y;
    const int z   = blockIdx.z;
    const int h   = bh % Hh;
    const int b   = bh / Hh;

    const float* Wm = (z == 0) ? Qw : (z == 1) ? Kw : Vw;

    #pragma unroll
    for (int it = 0; it < 32; ++it) {
        int idx = tid + it * 256;
        int e = idx >> 6, i = idx & 63;
        int s = s0 + i;
        float v = (s < Ss) ? x[((size_t)b * Ee + e) * Ss + s] : 0.f;
        xsd[i * 129 + e] = fdup(v);
    }
    const float* Wh = Wm + (size_t)h * Ee * Ee;
    #pragma unroll
    for (int it = 0; it < 64; ++it) {
        int idx = tid + it * 256;
        int kk = idx >> 7, f = idx & 127;
        ws[kk * 132 + f] = Wh[idx];
    }
    __syncthreads();

    const int rg = tid >> 4, cg = tid & 15;
    ull acc[4][4];
    #pragma unroll
    for (int j = 0; j < 4; ++j)
        #pragma unroll
        for (int c = 0; c < 4; ++c) acc[j][c] = 0ull;

    #pragma unroll 4
    for (int kk = 0; kk < 128; ++kk) {
        ulonglong2 w0 = *(const ulonglong2*)&ws[kk * 132 + cg * 8];
        ulonglong2 w1 = *(const ulonglong2*)&ws[kk * 132 + cg * 8 + 4];
        #pragma unroll
        for (int j = 0; j < 4; ++j) {
            ull a = xsd[(rg * 4 + j) * 129 + kk];
            ffma2(acc[j][0], a, w0.x);
            ffma2(acc[j][1], a, w0.y);
            ffma2(acc[j][2], a, w1.x);
            ffma2(acc[j][3], a, w1.y);
        }
    }

    #pragma unroll
    for (int j = 0; j < 4; ++j) {
        int s = s0 + rg * 4 + j;
        if (s >= Ss) continue;
        if (z < 2) {
            float* dst = (z == 0) ? g_q : g_k;
            float4 r0, r1;
            r0.x = f2lo(acc[j][0]); r0.y = f2hi(acc[j][0]);
            r0.z = f2lo(acc[j][1]); r0.w = f2hi(acc[j][1]);
            r1.x = f2lo(acc[j][2]); r1.y = f2hi(acc[j][2]);
            r1.z = f2lo(acc[j][3]); r1.w = f2hi(acc[j][3]);
            float* p = dst + ((size_t)bh * Ss + s) * Ee + cg * 8;
            *(float4*)p = r0;
            *(float4*)(p + 4) = r1;
        } else {
            float vals[8];
            vals[0] = f2lo(acc[j][0]); vals[1] = f2hi(acc[j][0]);
            vals[2] = f2lo(acc[j][1]); vals[3] = f2hi(acc[j][1]);
            vals[4] = f2lo(acc[j][2]); vals[5] = f2hi(acc[j][2]);
            vals[6] = f2lo(acc[j][3]); vals[7] = f2hi(acc[j][3]);
            #pragma unroll
            for (int c = 0; c < 8; ++c)
                g_vt[((size_t)bh * Ee + cg * 8 + c) * VTS + s] = vals[c];
        }
    }
}

// =================================================================
// Kernel 2: scores via mma.sync bf16 3-way split (6 products).
// Writes scaled raw logits to atten. Grid (81, 72), 256 thr.
// smem: A levels 0..2, B levels 0..2, each 128 x TPITCH bf16
// =================================================================
__global__ __launch_bounds__(256) void scores_kernel(float* __restrict__ atten)
{
    extern __shared__ __align__(16) unsigned char sm[];
    __nv_bfloat16* tiles = (__nv_bfloat16*)sm;

    const int tid = threadIdx.x, wid = tid >> 5, lane = tid & 31;
    const int mt_blk = blockIdx.x / 9, nt_blk = blockIdx.x % 9;
    const int bh = blockIdx.y;
    const int m0 = mt_blk * 128, n0 = nt_blk * 128;

    const float* gq = g_q + (size_t)bh * Ss * Ee;
    const float* gk = g_k + (size_t)bh * Ss * Ee;

    // ---- load + 3-way split into smem tiles ----
    for (int idx = tid; idx < 8192; idx += 256) {
        int r = idx >> 6, p = idx & 63;
        int soff = r * TPITCH + 2 * p;
        {
            int s = m0 + r;
            float2 v = (s < Ss) ? *(const float2*)&gq[(size_t)s * Ee + 2 * p]
                                : make_float2(0.f, 0.f);
            __nv_bfloat16 ax, bx, cx, ay, by, cy;
            split3(v.x, ax, bx, cx); split3(v.y, ay, by, cy);
            *(__nv_bfloat162*)&tiles[soff]           = __nv_bfloat162(ax, ay);
            *(__nv_bfloat162*)&tiles[TSZ + soff]     = __nv_bfloat162(bx, by);
            *(__nv_bfloat162*)&tiles[2 * TSZ + soff] = __nv_bfloat162(cx, cy);
        }
        {
            int t = n0 + r;
            float2 v = (t < Ss) ? *(const float2*)&gk[(size_t)t * Ee + 2 * p]
                                : make_float2(0.f, 0.f);
            __nv_bfloat16 ax, bx, cx, ay, by, cy;
            split3(v.x, ax, bx, cx); split3(v.y, ay, by, cy);
            *(__nv_bfloat162*)&tiles[3 * TSZ + soff] = __nv_bfloat162(ax, ay);
            *(__nv_bfloat162*)&tiles[4 * TSZ + soff] = __nv_bfloat162(bx, by);
            *(__nv_bfloat162*)&tiles[5 * TSZ + soff] = __nv_bfloat162(cx, cy);
        }
    }
    __syncthreads();

    // ---- mainloop ----
    const int wr = wid >> 2, wc = wid & 3;         // warp tile: rows wr*64, cols wc*32
    const int l15 = lane & 15;
    float acc[4][4][4];
    #pragma unroll
    for (int mt = 0; mt < 4; ++mt)
        #pragma unroll
        for (int nt = 0; nt < 4; ++nt)
            #pragma unroll
            for (int i = 0; i < 4; ++i) acc[mt][nt][i] = 0.f;

    const u32 sb = s2u(tiles);
    const int PA[6] = {0, 0, 1, 0, 1, 2};
    const int PB[6] = {0, 1, 0, 2, 1, 0};

    for (int l = 0; l < 6; ++l) {
        u32 abase = sb + (u32)(PA[l] * TSZ) * 2;
        u32 bbase = sb + (u32)((3 + PB[l]) * TSZ) * 2;
        #pragma unroll
        for (int k = 0; k < 8; ++k) {
            const int k0 = k * 16;
            u32 bfrag[4][2];
            u32 brow = bbase + (u32)((wc * 32 + (l15 & 7)) * TPITCH + k0 + ((l15 >> 3) * 8)) * 2;
            #pragma unroll
            for (int nt = 0; nt < 4; ++nt)
                ldmx2(bfrag[nt][0], bfrag[nt][1], brow + (u32)(nt * 8 * TPITCH) * 2);
            u32 arow = abase + (u32)((wr * 64 + l15) * TPITCH + k0 + ((lane >> 4) * 8)) * 2;
            #pragma unroll
            for (int mt = 0; mt < 4; ++mt) {
                u32 a0, a1, a2, a3;
                ldmx4(a0, a1, a2, a3, arow + (u32)(mt * 16 * TPITCH) * 2);
                #pragma unroll
                for (int nt = 0; nt < 4; ++nt)
                    mma16816(acc[mt][nt], a0, a1, a2, a3, bfrag[nt][0], bfrag[nt][1]);
            }
        }
    }
    __syncthreads();

    // ---- epilogue: regs -> stage smem -> coalesced gmem (scaled) ----
    float* stage = (float*)sm;   // [128][130]
    {
        int row = wr * 64 + (lane >> 2);
        int col = wc * 32 + (lane & 3) * 2;
        #pragma unroll
        for (int mt = 0; mt < 4; ++mt)
            #pragma unroll
            for (int nt = 0; nt < 4; ++nt) {
                float* c = acc[mt][nt];
                int rr = row + mt * 16, cc = col + nt * 8;
                *(float2*)&stage[rr * 130 + cc]       = make_float2(c[0], c[1]);
                *(float2*)&stage[(rr + 8) * 130 + cc] = make_float2(c[2], c[3]);
            }
    }
    __syncthreads();
    const float scl = 0.08838834764831845f;  // 1/sqrt(128)
    for (int idx = tid; idx < 128 * 128; idx += 256) {
        int rr = idx >> 7, c = idx & 127;
        int s = m0 + rr, t = n0 + c;
        if (s < Ss && t < Ss)
            atten[((size_t)bh * Ss + s) * Ss + t] = stage[rr * 130 + c] * scl;
    }
}

// =================================================================
// Kernel 3: in-place softmax over each atten row. Grid = B*H*S, 128 thr.
// =================================================================
__global__ __launch_bounds__(128) void softmax_kernel(float* __restrict__ atten)
{
    __shared__ float buf[Ss];
    __shared__ float redm[4], reds[4];
    const int tid = threadIdx.x, wid = tid >> 5, lid = tid & 31;
    float* p = atten + (size_t)blockIdx.x * Ss;

    float m = -3.0e38f;
    for (int c = tid; c < Ss; c += 128) { float v = p[c]; buf[c] = v; m = fmaxf(m, v); }
    #pragma unroll
    for (int o = 16; o; o >>= 1) m = fmaxf(m, __shfl_xor_sync(0xffffffffu, m, o));
    if (lid == 0) redm[wid] = m;
    __syncthreads();
    m = fmaxf(fmaxf(redm[0], redm[1]), fmaxf(redm[2], redm[3]));

    float sum = 0.f;
    for (int c = tid; c < Ss; c += 128) { float e = __expf(buf[c] - m); buf[c] = e; sum += e; }
    #pragma unroll
    for (int o = 16; o; o >>= 1) sum += __shfl_xor_sync(0xffffffffu, sum, o);
    if (lid == 0) reds[wid] = sum;
    __syncthreads();
    float inv = 1.f / (reds[0] + reds[1] + reds[2] + reds[3]);
    for (int c = tid; c < Ss; c += 128) p[c] = buf[c] * inv;
}

// =================================================================
// Kernel 4: AV via mma.sync bf16 2-way split (3 products), 9 k-chunks.
// Grid (9, 72), 256 thr. smem: P1 P2 V1 V2 tiles (128 x TPITCH bf16 each)
// =================================================================
__global__ __launch_bounds__(256) void av_kernel(const float* __restrict__ atten)
{
    extern __shared__ __align__(16) unsigned char sm[];
    __nv_bfloat16* tiles = (__nv_bfloat16*)sm;   // P1 | P2 | V1 | V2

    const int tid = threadIdx.x, wid = tid >> 5, lane = tid & 31;
    const int mt_blk = blockIdx.x;
    const int bh = blockIdx.y;
    const int b = bh / Hh, h = bh % Hh;
    const int m0 = mt_blk * 128;

    const float* prow = atten + (size_t)bh * Ss * Ss;
    const float* vrow = g_vt + (size_t)bh * Ee * VTS;

    const int wr = wid >> 2, wc = wid & 3;
    const int l15 = lane & 15;
    float acc[4][4][4];
    #pragma unroll
    for (int mt = 0; mt < 4; ++mt)
        #pragma unroll
        for (int nt = 0; nt < 4; ++nt)
            #pragma unroll
            for (int i = 0; i < 4; ++i) acc[mt][nt][i] = 0.f;

    const u32 sb = s2u(tiles);

    for (int ck = 0; ck < 9; ++ck) {
        const int c0 = ck * 128;
        // P chunk (A row-major [s][t]), scalar guarded loads (odd row stride)
        for (int idx = tid; idx < 8192; idx += 256) {
            int r = idx >> 6, pp = idx & 63;
            int s = m0 + r, t = c0 + 2 * pp;
            float x0 = (s < Ss && t < Ss)     ? prow[(size_t)s * Ss + t]     : 0.f;
            float x1 = (s < Ss && t + 1 < Ss) ? prow[(size_t)s * Ss + t + 1] : 0.f;
            __nv_bfloat16 a0, b0, a1, b1;
            split2(x0, a0, b0); split2(x1, a1, b1);
            int soff = r * TPITCH + 2 * pp;
            *(__nv_bfloat162*)&tiles[soff]       = __nv_bfloat162(a0, a1);
            *(__nv_bfloat162*)&tiles[TSZ + soff] = __nv_bfloat162(b0, b1);
        }
        // V chunk (B as [n=f][k=t] row-major = col-major for mma)
        for (int idx = tid; idx < 8192; idx += 256) {
            int f = idx >> 6, pp = idx & 63;
            int t = c0 + 2 * pp;
            float2 v;
            if (t + 1 < Ss) v = *(const float2*)&vrow[(size_t)f * VTS + t];
            else { v.x = (t < Ss) ? vrow[(size_t)f * VTS + t] : 0.f; v.y = 0.f; }
            __nv_bfloat16 a0, b0, a1, b1;
            split2(v.x, a0, b0); split2(v.y, a1, b1);
            int soff = f * TPITCH + 2 * pp;
            *(__nv_bfloat162*)&tiles[2 * TSZ + soff] = __nv_bfloat162(a0, a1);
            *(__nv_bfloat162*)&tiles[3 * TSZ + soff] = __nv_bfloat162(b0, b1);
        }
        __syncthreads();

        const int PAv[3] = {0, 0, 1};
        const int PBv[3] = {2, 3, 2};
        #pragma unroll
        for (int l = 0; l < 3; ++l) {
            u32 abase = sb + (u32)(PAv[l] * TSZ) * 2;
            u32 bbase = sb + (u32)(PBv[l] * TSZ) * 2;
            #pragma unroll
            for (int k = 0; k < 8; ++k) {
                const int k0 = k * 16;
                u32 bfrag[4][2];
                u32 brow = bbase + (u32)((wc * 32 + (l15 & 7)) * TPITCH + k0 + ((l15 >> 3) * 8)) * 2;
                #pragma unroll
                for (int nt = 0; nt < 4; ++nt)
                    ldmx2(bfrag[nt][0], bfrag[nt][1], brow + (u32)(nt * 8 * TPITCH) * 2);
                u32 arow = abase + (u32)((wr * 64 + l15) * TPITCH + k0 + ((lane >> 4) * 8)) * 2;
                #pragma unroll
                for (int mt = 0; mt < 4; ++mt) {
                    u32 a0, a1, a2, a3;
                    ldmx4(a0, a1, a2, a3, arow + (u32)(mt * 16 * TPITCH) * 2);
                    #pragma unroll
                    for (int nt = 0; nt < 4; ++nt)
                        mma16816(acc[mt][nt], a0, a1, a2, a3, bfrag[nt][0], bfrag[nt][1]);
                }
            }
        }
        __syncthreads();
    }

    // ---- epilogue: regs -> stage -> g_ho (float4 coalesced) ----
    float* stage = (float*)sm;   // [128][130]
    {
        int row = wr * 64 + (lane >> 2);
        int col = wc * 32 + (lane & 3) * 2;
        #pragma unroll
        for (int mt = 0; mt < 4; ++mt)
            #pragma unroll
            for (int nt = 0; nt < 4; ++nt) {
                float* c = acc[mt][nt];
                int rr = row + mt * 16, cc = col + nt * 8;
                *(float2*)&stage[rr * 130 + cc]       = make_float2(c[0], c[1]);
                *(float2*)&stage[(rr + 8) * 130 + cc] = make_float2(c[2], c[3]);
            }
    }
    __syncthreads();
    for (int idx = tid; idx < 128 * 32; idx += 256) {
        int rr = idx >> 5, q4 = idx & 31;
        int s = m0 + rr;
        if (s < Ss) {
            float4 v;
            v.x = stage[rr * 130 + q4 * 4];
            v.y = stage[rr * 130 + q4 * 4 + 1];
            v.z = stage[rr * 130 + q4 * 4 + 2];
            v.w = stage[rr * 130 + q4 * 4 + 3];
            *(float4*)&g_ho[((size_t)b * Ss + s) * HE + h * Ee + q4 * 4] = v;
        }
    }
}

// =================================================================
// Kernel 5: out[b,e,s] = g_ho[b,s,:] . W[e,:] + bias[e] (fp32 f32x2)
// =================================================================
__global__ __launch_bounds__(256) void outproj_kernel(
    const float* __restrict__ Wm, const float* __restrict__ bias,
    float* __restrict__ out)
{
    __shared__ __align__(16) ull   Asd[64 * 33];
    __shared__ __align__(16) float Ws[32 * 132];

    const int tid  = threadIdx.x;
    const int row0 = blockIdx.x * 64;
    const int rg = tid >> 4, cg = tid & 15;

    ull acc[4][4];
    #pragma unroll
    for (int j = 0; j < 4; ++j)
        #pragma unroll
        for (int c = 0; c < 4; ++c) acc[j][c] = 0ull;

    for (int k0 = 0; k0 < HE; k0 += 32) {
        __syncthreads();
        #pragma unroll
        for (int it = 0; it < 8; ++it) {
            int idx = tid + it * 256;
            int i = idx >> 5, kk = idx & 31;
            int row = row0 + i;
            float v = (row < Bb * Ss) ? g_ho[(size_t)row * HE + k0 + kk] : 0.f;
            Asd[i * 33 + kk] = fdup(v);
        }
        #pragma unroll
        for (int it = 0; it < 16; ++it) {
            int idx = tid + it * 256;
            int e = idx >> 5, kk = idx & 31;
            Ws[kk * 132 + e] = Wm[(size_t)e * HE + k0 + kk];
        }
        __syncthreads();
        #pragma unroll 4
        for (int kk = 0; kk < 32; ++kk) {
            ulonglong2 w0 = *(const ulonglong2*)&Ws[kk * 132 + cg * 8];
            ulonglong2 w1 = *(const ulonglong2*)&Ws[kk * 132 + cg * 8 + 4];
            #pragma unroll
            for (int j = 0; j < 4; ++j) {
                ull a = Asd[(rg * 4 + j) * 33 + kk];
                ffma2(acc[j][0], a, w0.x);
                ffma2(acc[j][1], a, w0.y);
                ffma2(acc[j][2], a, w1.x);
                ffma2(acc[j][3], a, w1.y);
            }
        }
    }

    #pragma unroll
    for (int j = 0; j < 4; ++j) {
        int row = row0 + rg * 4 + j;
        if (row < Bb * Ss) {
            int b = row / Ss, s = row % Ss;
            float* obase = out + (size_t)b * Ee * Ss + s;
            #pragma unroll
            for (int c = 0; c < 4; ++c) {
                int e = cg * 8 + c * 2;
                obase[(size_t)e * Ss]       = f2lo(acc[j][c]) + bias[e];
                obase[(size_t)(e + 1) * Ss] = f2hi(acc[j][c]) + bias[e + 1];
            }
        }
    }
}

// =================================================================
extern "C" void kernel_launch(void* const* d_in, const int* in_sizes, int n_in,
                              void* d_out, int out_size)
{
    const float* x    = (const float*)d_in[0];
    const float* Qw   = (const float*)d_in[1];
    const float* Kw   = (const float*)d_in[2];
    const float* Vw   = (const float*)d_in[3];
    const float* Wm   = (const float*)d_in[4];
    const float* bias = (const float*)d_in[5];

    float* out   = (float*)d_out;                    // [B,E,S]
    float* atten = out + (size_t)Bb * Ee * Ss;       // [B,H,S,S]

    const int smem1 = 64 * 129 * 8 + 128 * 132 * 4;  // 133,632
    const int smemS = 6 * TSZ * 2;                   // 208,896
    const int smemA = 4 * TSZ * 2;                   // 139,264

    cudaFuncSetAttribute(proj_kernel,   cudaFuncAttributeMaxDynamicSharedMemorySize, smem1);
    cudaFuncSetAttribute(scores_kernel, cudaFuncAttributeMaxDynamicSharedMemorySize, smemS);
    cudaFuncSetAttribute(av_kernel,     cudaFuncAttributeMaxDynamicSharedMemorySize, smemA);

    proj_kernel<<<dim3(17, Bb * Hh, 3), 256, smem1>>>(x, Qw, Kw, Vw);
    scores_kernel<<<dim3(81, Bb * Hh), 256, smemS>>>(atten);
    softmax_kernel<<<Bb * Hh * Ss, 128>>>(atten);
    av_kernel<<<dim3(9, Bb * Hh), 256, smemA>>>(atten);
    outproj_kernel<<<129, 256>>>(Wm, bias, out);
}

// round 4
// speedup vs baseline: 1.5765x; 1.5765x over previous
#include <cuda_runtime.h>
#include <cuda_bf16.h>

#define Bb 8
#define Hh 9
#define Ee 128
#define Ss 1025
#define SPAD 1152   // padded sequence (rows >=1025 stay zero-initialized)
#define HE 1152
#define QP 72       // bf16 pitch for [128 x 64] k-chunk tiles (A and scores-B)
#define VP 136      // bf16 pitch for [64 x 128] V tiles (B-trans)
#define ATILE 18432 // 128*72*2 bytes
#define VTILE 17408 // 64*136*2 bytes

typedef unsigned long long ull;
typedef unsigned int u32;

// ---------------- scratch (zero-initialized BSS; padding rows never written) ----
__device__ __nv_bfloat16 g_q0[72 * SPAD * 128], g_q1[72 * SPAD * 128], g_q2[72 * SPAD * 128];
__device__ __nv_bfloat16 g_k0[72 * SPAD * 128], g_k1[72 * SPAD * 128], g_k2[72 * SPAD * 128];
__device__ __nv_bfloat16 g_v1[72 * SPAD * 128], g_v2[72 * SPAD * 128];
__device__ __nv_bfloat16 g_p1[(size_t)72 * SPAD * SPAD], g_p2[(size_t)72 * SPAD * SPAD];
__device__ float g_ho[Bb * Ss * HE];

// ---------------- f32x2 helpers ----------------
__device__ __forceinline__ ull fdup(float v) {
    unsigned u = __float_as_uint(v);
    return ((ull)u << 32) | (ull)u;
}
__device__ __forceinline__ void ffma2(ull& d, ull a, ull b) {
    asm("fma.rn.f32x2 %0, %1, %2, %0;" : "+l"(d) : "l"(a), "l"(b));
}
__device__ __forceinline__ float f2lo(ull v) { return __uint_as_float((unsigned)v); }
__device__ __forceinline__ float f2hi(ull v) { return __uint_as_float((unsigned)(v >> 32)); }

// ---------------- async copy / mma helpers ----------------
__device__ __forceinline__ u32 s2u(const void* p) {
    u32 a;
    asm("{ .reg .u64 t; cvta.to.shared.u64 t, %1; cvt.u32.u64 %0, t; }" : "=r"(a) : "l"(p));
    return a;
}
__device__ __forceinline__ void cp16(u32 smem, const void* g) {
    asm volatile("cp.async.cg.shared.global [%0], [%1], 16;" :: "r"(smem), "l"(g));
}
__device__ __forceinline__ void cp_commit() { asm volatile("cp.async.commit_group;" ::: "memory"); }
template <int N> __device__ __forceinline__ void cp_wait() {
    asm volatile("cp.async.wait_group %0;" :: "n"(N) : "memory");
}
__device__ __forceinline__ void ldmx4(u32& a0, u32& a1, u32& a2, u32& a3, u32 addr) {
    asm volatile("ldmatrix.sync.aligned.m8n8.x4.shared.b16 {%0,%1,%2,%3}, [%4];"
                 : "=r"(a0), "=r"(a1), "=r"(a2), "=r"(a3) : "r"(addr));
}
__device__ __forceinline__ void ldmx2(u32& b0, u32& b1, u32 addr) {
    asm volatile("ldmatrix.sync.aligned.m8n8.x2.shared.b16 {%0,%1}, [%2];"
                 : "=r"(b0), "=r"(b1) : "r"(addr));
}
__device__ __forceinline__ void ldmx2t(u32& b0, u32& b1, u32 addr) {
    asm volatile("ldmatrix.sync.aligned.m8n8.x2.trans.shared.b16 {%0,%1}, [%2];"
                 : "=r"(b0), "=r"(b1) : "r"(addr));
}
__device__ __forceinline__ void mma16816(float* c, u32 a0, u32 a1, u32 a2, u32 a3,
                                         u32 b0, u32 b1) {
    asm volatile("mma.sync.aligned.m16n8k16.row.col.f32.bf16.bf16.f32 "
                 "{%0,%1,%2,%3}, {%4,%5,%6,%7}, {%8,%9}, {%0,%1,%2,%3};"
                 : "+f"(c[0]), "+f"(c[1]), "+f"(c[2]), "+f"(c[3])
                 : "r"(a0), "r"(a1), "r"(a2), "r"(a3), "r"(b0), "r"(b1));
}

// =================================================================
// Kernel 1: projections (fp32 f32x2), emitting bf16 splits.
// z=0 -> q (3-way), z=1 -> k (3-way), z=2 -> v (2-way). All [bh][s][f].
// =================================================================
__global__ __launch_bounds__(256) void proj_kernel(
    const float* __restrict__ x, const float* __restrict__ Qw,
    const float* __restrict__ Kw, const float* __restrict__ Vw)
{
    extern __shared__ unsigned char sm1[];
    ull*   xsd = (ull*)sm1;                      // [64][129] duplicated pairs
    float* ws  = (float*)(sm1 + 64 * 129 * 8);   // [128][132]

    const int tid = threadIdx.x;
    const int s0  = blockIdx.x * 64;
    const int bh  = blockIdx.y;
    const int z   = blockIdx.z;
    const int h   = bh % Hh;
    const int b   = bh / Hh;

    const float* Wm = (z == 0) ? Qw : (z == 1) ? Kw : Vw;

    #pragma unroll
    for (int it = 0; it < 32; ++it) {
        int idx = tid + it * 256;
        int e = idx >> 6, i = idx & 63;
        int s = s0 + i;
        float v = (s < Ss) ? x[((size_t)b * Ee + e) * Ss + s] : 0.f;
        xsd[i * 129 + e] = fdup(v);
    }
    const float* Wh = Wm + (size_t)h * Ee * Ee;
    #pragma unroll
    for (int it = 0; it < 64; ++it) {
        int idx = tid + it * 256;
        int kk = idx >> 7, f = idx & 127;
        ws[kk * 132 + f] = Wh[idx];
    }
    __syncthreads();

    const int rg = tid >> 4, cg = tid & 15;
    ull acc[4][4];
    #pragma unroll
    for (int j = 0; j < 4; ++j)
        #pragma unroll
        for (int c = 0; c < 4; ++c) acc[j][c] = 0ull;

    #pragma unroll 4
    for (int kk = 0; kk < 128; ++kk) {
        ulonglong2 w0 = *(const ulonglong2*)&ws[kk * 132 + cg * 8];
        ulonglong2 w1 = *(const ulonglong2*)&ws[kk * 132 + cg * 8 + 4];
        #pragma unroll
        for (int j = 0; j < 4; ++j) {
            ull a = xsd[(rg * 4 + j) * 129 + kk];
            ffma2(acc[j][0], a, w0.x);
            ffma2(acc[j][1], a, w0.y);
            ffma2(acc[j][2], a, w1.x);
            ffma2(acc[j][3], a, w1.y);
        }
    }

    __nv_bfloat16* d0 = (z == 0) ? g_q0 : (z == 1) ? g_k0 : g_v1;
    __nv_bfloat16* d1 = (z == 0) ? g_q1 : (z == 1) ? g_k1 : g_v2;
    __nv_bfloat16* d2 = (z == 0) ? g_q2 : g_k2;   // unused when z==2

    #pragma unroll
    for (int j = 0; j < 4; ++j) {
        int s = s0 + rg * 4 + j;
        if (s >= Ss) continue;
        float vals[8];
        vals[0] = f2lo(acc[j][0]); vals[1] = f2hi(acc[j][0]);
        vals[2] = f2lo(acc[j][1]); vals[3] = f2hi(acc[j][1]);
        vals[4] = f2lo(acc[j][2]); vals[5] = f2hi(acc[j][2]);
        vals[6] = f2lo(acc[j][3]); vals[7] = f2hi(acc[j][3]);
        union { uint4 u; __nv_bfloat16 h[8]; } p0, p1, p2;
        #pragma unroll
        for (int c = 0; c < 8; ++c) {
            float v = vals[c];
            p0.h[c] = __float2bfloat16(v);
            float r = v - __bfloat162float(p0.h[c]);
            p1.h[c] = __float2bfloat16(r);
            float r2 = r - __bfloat162float(p1.h[c]);
            p2.h[c] = __float2bfloat16(r2);
        }
        size_t base = ((size_t)bh * SPAD + s) * 128 + cg * 8;
        *(uint4*)&d0[base] = p0.u;
        *(uint4*)&d1[base] = p1.u;
        if (z < 2) *(uint4*)&d2[base] = p2.u;
    }
}

// =================================================================
// Kernel 2: scores. Pure bf16 GEMM, 3-way split (6 products), K=128 as
// two k64 chunks (cp.async double-buffered). Grid (81, 72), 256 thr.
// smem: 2 stages x 6 tiles x [128][QP] bf16 = 221,184 B
// =================================================================
__global__ __launch_bounds__(256) void scores_kernel(float* __restrict__ atten)
{
    extern __shared__ __align__(16) unsigned char sm[];
    const u32 sbase = s2u(sm);
    const int tid = threadIdx.x, wid = tid >> 5, lane = tid & 31;
    const int m0 = (blockIdx.x / 9) * 128, n0r = (blockIdx.x % 9) * 128;
    const int bh = blockIdx.y;
    const int wr = wid >> 2, wc = wid & 3;
    const int l15 = lane & 15;

    const __nv_bfloat16* srcs[6] = {g_q0, g_q1, g_q2, g_k0, g_k1, g_k2};

    // issue both chunk loads up front (chunk kc -> stage kc)
    #pragma unroll
    for (int kc = 0; kc < 2; ++kc) {
        const int e0 = kc * 64;
        for (int i = tid; i < 6 * 1024; i += 256) {
            int t = i >> 10, rc = i & 1023, r = rc >> 3, c = rc & 7;
            int row0 = (t < 3) ? m0 : n0r;
            const __nv_bfloat16* g = srcs[t] + ((size_t)bh * SPAD + row0 + r) * 128 + e0 + c * 8;
            cp16(sbase + kc * (6 * ATILE) + t * ATILE + (r * QP + c * 8) * 2, g);
        }
        cp_commit();
    }

    float acc[4][4][4];
    #pragma unroll
    for (int mt = 0; mt < 4; ++mt)
        #pragma unroll
        for (int nt = 0; nt < 4; ++nt)
            #pragma unroll
            for (int i = 0; i < 4; ++i) acc[mt][nt][i] = 0.f;

    #pragma unroll
    for (int kc = 0; kc < 2; ++kc) {
        if (kc == 0) cp_wait<1>(); else cp_wait<0>();
        __syncthreads();
        const u32 st = sbase + kc * (6 * ATILE);
        const int PA[6] = {0, 0, 1, 0, 1, 2};
        const int PB[6] = {0, 1, 0, 2, 1, 0};
        #pragma unroll
        for (int l = 0; l < 6; ++l) {
            u32 abase = st + PA[l] * ATILE;
            u32 bbase = st + (3 + PB[l]) * ATILE;
            #pragma unroll
            for (int k = 0; k < 4; ++k) {
                const int k0 = k * 16;
                u32 bfrag[4][2];
                u32 brow = bbase + ((wc * 32 + (l15 & 7)) * QP + k0 + ((l15 >> 3) * 8)) * 2;
                #pragma unroll
                for (int nt = 0; nt < 4; ++nt)
                    ldmx2(bfrag[nt][0], bfrag[nt][1], brow + (nt * 8 * QP) * 2);
                u32 arow = abase + ((wr * 64 + l15) * QP + k0 + ((lane >> 4) * 8)) * 2;
                #pragma unroll
                for (int mt = 0; mt < 4; ++mt) {
                    u32 a0, a1, a2, a3;
                    ldmx4(a0, a1, a2, a3, arow + (mt * 16 * QP) * 2);
                    #pragma unroll
                    for (int nt = 0; nt < 4; ++nt)
                        mma16816(acc[mt][nt], a0, a1, a2, a3, bfrag[nt][0], bfrag[nt][1]);
                }
            }
        }
        __syncthreads();
    }

    // epilogue: regs -> stage smem -> coalesced gmem (scaled)
    float* stage = (float*)sm;   // [128][130]
    {
        int row = wr * 64 + (lane >> 2);
        int col = wc * 32 + (lane & 3) * 2;
        #pragma unroll
        for (int mt = 0; mt < 4; ++mt)
            #pragma unroll
            for (int nt = 0; nt < 4; ++nt) {
                float* c = acc[mt][nt];
                int rr = row + mt * 16, cc = col + nt * 8;
                *(float2*)&stage[rr * 130 + cc]       = make_float2(c[0], c[1]);
                *(float2*)&stage[(rr + 8) * 130 + cc] = make_float2(c[2], c[3]);
            }
    }
    __syncthreads();
    const float scl = 0.08838834764831845f;  // 1/sqrt(128)
    for (int idx = tid; idx < 128 * 128; idx += 256) {
        int rr = idx >> 7, c = idx & 127;
        int s = m0 + rr, t = n0r + c;
        if (s < Ss && t < Ss)
            atten[((size_t)bh * Ss + s) * Ss + t] = stage[rr * 130 + c] * scl;
    }
}

// =================================================================
// Kernel 3: softmax per row; writes fp32 atten AND bf16 2-way split of P.
// Grid = B*H*S, 128 thr.
// =================================================================
__global__ __launch_bounds__(128) void softmax_kernel(float* __restrict__ atten)
{
    __shared__ float buf[Ss];
    __shared__ float redm[4], reds[4];
    const int tid = threadIdx.x, wid = tid >> 5, lid = tid & 31;
    const int row = blockIdx.x;
    const int bh = row / Ss, s = row % Ss;
    float* p = atten + (size_t)row * Ss;

    float m = -3.0e38f;
    for (int c = tid; c < Ss; c += 128) { float v = p[c]; buf[c] = v; m = fmaxf(m, v); }
    #pragma unroll
    for (int o = 16; o; o >>= 1) m = fmaxf(m, __shfl_xor_sync(0xffffffffu, m, o));
    if (lid == 0) redm[wid] = m;
    __syncthreads();
    m = fmaxf(fmaxf(redm[0], redm[1]), fmaxf(redm[2], redm[3]));

    float sum = 0.f;
    for (int c = tid; c < Ss; c += 128) { float e = __expf(buf[c] - m); buf[c] = e; sum += e; }
    #pragma unroll
    for (int o = 16; o; o >>= 1) sum += __shfl_xor_sync(0xffffffffu, sum, o);
    if (lid == 0) reds[wid] = sum;
    __syncthreads();
    float inv = 1.f / (reds[0] + reds[1] + reds[2] + reds[3]);

    size_t pbase = ((size_t)bh * SPAD + s) * SPAD;
    for (int c = tid; c < Ss; c += 128) {
        float pr = buf[c] * inv;
        p[c] = pr;
        __nv_bfloat16 hi = __float2bfloat16(pr);
        g_p1[pbase + c] = hi;
        g_p2[pbase + c] = __float2bfloat16(pr - __bfloat162float(hi));
    }
}

// =================================================================
// Kernel 4: AV. bf16 2-way split (3 products), 18 k64 chunks, cp.async
// double-buffered, V via ldmatrix.trans. Grid (9, 72), 256 thr.
// smem: 2 stages x (2 P tiles [128][QP] + 2 V tiles [64][VP]) = 143,360 B
// =================================================================
__global__ __launch_bounds__(256) void av_kernel()
{
    extern __shared__ __align__(16) unsigned char sm[];
    const u32 sbase = s2u(sm);
    const int tid = threadIdx.x, wid = tid >> 5, lane = tid & 31;
    const int m0 = blockIdx.x * 128;
    const int bh = blockIdx.y;
    const int b = bh / Hh, h = bh % Hh;
    const int wr = wid >> 2, wc = wid & 3;
    const int l15 = lane & 15;
    const int STG = 2 * ATILE + 2 * VTILE;   // 71,680

    auto load_chunk = [&](int st, int ck) {
        const int t0 = ck * 64;
        for (int i = tid; i < 4096; i += 256) {
            if (i < 2048) {
                int t = i >> 10, r = (i >> 3) & 127, c = i & 7;
                const __nv_bfloat16* g = (t ? g_p2 : g_p1) +
                    ((size_t)bh * SPAD + m0 + r) * SPAD + t0 + c * 8;
                cp16(sbase + st * STG + t * ATILE + (r * QP + c * 8) * 2, g);
            } else {
                int j = i - 2048;
                int t = j >> 10, r = (j >> 4) & 63, c = j & 15;
                const __nv_bfloat16* g = (t ? g_v2 : g_v1) +
                    ((size_t)bh * SPAD + t0 + r) * 128 + c * 8;
                cp16(sbase + st * STG + 2 * ATILE + t * VTILE + (r * VP + c * 8) * 2, g);
            }
        }
        cp_commit();
    };

    float acc[4][4][4];
    #pragma unroll
    for (int mt = 0; mt < 4; ++mt)
        #pragma unroll
        for (int nt = 0; nt < 4; ++nt)
            #pragma unroll
            for (int i = 0; i < 4; ++i) acc[mt][nt][i] = 0.f;

    load_chunk(0, 0);

    for (int ck = 0; ck < 18; ++ck) {
        if (ck + 1 < 18) load_chunk((ck + 1) & 1, ck + 1);
        if (ck + 1 < 18) cp_wait<1>(); else cp_wait<0>();
        __syncthreads();

        const u32 st = sbase + (ck & 1) * STG;
        const int PA[3] = {0, 0, 1};
        const int PB[3] = {0, 1, 0};
        #pragma unroll
        for (int l = 0; l < 3; ++l) {
            u32 abase = st + PA[l] * ATILE;
            u32 bbase = st + 2 * ATILE + PB[l] * VTILE;
            #pragma unroll
            for (int k = 0; k < 4; ++k) {
                const int k0 = k * 16;
                u32 bfrag[4][2];
                u32 brow = bbase + ((k0 + l15) * VP) * 2;
                #pragma unroll
                for (int nt = 0; nt < 4; ++nt)
                    ldmx2t(bfrag[nt][0], bfrag[nt][1], brow + (wc * 32 + nt * 8) * 2);
                u32 arow = abase + ((wr * 64 + l15) * QP + k0 + ((lane >> 4) * 8)) * 2;
                #pragma unroll
                for (int mt = 0; mt < 4; ++mt) {
                    u32 a0, a1, a2, a3;
                    ldmx4(a0, a1, a2, a3, arow + (mt * 16 * QP) * 2);
                    #pragma unroll
                    for (int nt = 0; nt < 4; ++nt)
                        mma16816(acc[mt][nt], a0, a1, a2, a3, bfrag[nt][0], bfrag[nt][1]);
                }
            }
        }
        __syncthreads();
    }

    // epilogue: regs -> stage -> g_ho (float4 coalesced)
    float* stage = (float*)sm;   // [128][130]
    {
        int row = wr * 64 + (lane >> 2);
        int col = wc * 32 + (lane & 3) * 2;
        #pragma unroll
        for (int mt = 0; mt < 4; ++mt)
            #pragma unroll
            for (int nt = 0; nt < 4; ++nt) {
                float* c = acc[mt][nt];
                int rr = row + mt * 16, cc = col + nt * 8;
                *(float2*)&stage[rr * 130 + cc]       = make_float2(c[0], c[1]);
                *(float2*)&stage[(rr + 8) * 130 + cc] = make_float2(c[2], c[3]);
            }
    }
    __syncthreads();
    for (int idx = tid; idx < 128 * 32; idx += 256) {
        int rr = idx >> 5, q4 = idx & 31;
        int s = m0 + rr;
        if (s < Ss) {
            float4 v;
            v.x = stage[rr * 130 + q4 * 4];
            v.y = stage[rr * 130 + q4 * 4 + 1];
            v.z = stage[rr * 130 + q4 * 4 + 2];
            v.w = stage[rr * 130 + q4 * 4 + 3];
            *(float4*)&g_ho[((size_t)b * Ss + s) * HE + h * Ee + q4 * 4] = v;
        }
    }
}

// =================================================================
// Kernel 5: out[b,e,s] = g_ho[b,s,:] . W[e,:] + bias[e] (fp32 f32x2)
// =================================================================
__global__ __launch_bounds__(256) void outproj_kernel(
    const float* __restrict__ Wm, const float* __restrict__ bias,
    float* __restrict__ out)
{
    __shared__ __align__(16) ull   Asd[64 * 33];
    __shared__ __align__(16) float Ws[32 * 132];

    const int tid  = threadIdx.x;
    const int row0 = blockIdx.x * 64;
    const int rg = tid >> 4, cg = tid & 15;

    ull acc[4][4];
    #pragma unroll
    for (int j = 0; j < 4; ++j)
        #pragma unroll
        for (int c = 0; c < 4; ++c) acc[j][c] = 0ull;

    for (int k0 = 0; k0 < HE; k0 += 32) {
        __syncthreads();
        #pragma unroll
        for (int it = 0; it < 8; ++it) {
            int idx = tid + it * 256;
            int i = idx >> 5, kk = idx & 31;
            int row = row0 + i;
            float v = (row < Bb * Ss) ? g_ho[(size_t)row * HE + k0 + kk] : 0.f;
            Asd[i * 33 + kk] = fdup(v);
        }
        #pragma unroll
        for (int it = 0; it < 16; ++it) {
            int idx = tid + it * 256;
            int e = idx >> 5, kk = idx & 31;
            Ws[kk * 132 + e] = Wm[(size_t)e * HE + k0 + kk];
        }
        __syncthreads();
        #pragma unroll 4
        for (int kk = 0; kk < 32; ++kk) {
            ulonglong2 w0 = *(const ulonglong2*)&Ws[kk * 132 + cg * 8];
            ulonglong2 w1 = *(const ulonglong2*)&Ws[kk * 132 + cg * 8 + 4];
            #pragma unroll
            for (int j = 0; j < 4; ++j) {
                ull a = Asd[(rg * 4 + j) * 33 + kk];
                ffma2(acc[j][0], a, w0.x);
                ffma2(acc[j][1], a, w0.y);
                ffma2(acc[j][2], a, w1.x);
                ffma2(acc[j][3], a, w1.y);
            }
        }
    }

    #pragma unroll
    for (int j = 0; j < 4; ++j) {
        int row = row0 + rg * 4 + j;
        if (row < Bb * Ss) {
            int b = row / Ss, s = row % Ss;
            float* obase = out + (size_t)b * Ee * Ss + s;
            #pragma unroll
            for (int c = 0; c < 4; ++c) {
                int e = cg * 8 + c * 2;
                obase[(size_t)e * Ss]       = f2lo(acc[j][c]) + bias[e];
                obase[(size_t)(e + 1) * Ss] = f2hi(acc[j][c]) + bias[e + 1];
            }
        }
    }
}

// =================================================================
extern "C" void kernel_launch(void* const* d_in, const int* in_sizes, int n_in,
                              void* d_out, int out_size)
{
    const float* x    = (const float*)d_in[0];
    const float* Qw   = (const float*)d_in[1];
    const float* Kw   = (const float*)d_in[2];
    const float* Vw   = (const float*)d_in[3];
    const float* Wm   = (const float*)d_in[4];
    const float* bias = (const float*)d_in[5];

    float* out   = (float*)d_out;                    // [B,E,S]
    float* atten = out + (size_t)Bb * Ee * Ss;       // [B,H,S,S]

    const int smem1 = 64 * 129 * 8 + 128 * 132 * 4;  // 133,632
    const int smemS = 2 * 6 * ATILE;                 // 221,184
    const int smemA = 2 * (2 * ATILE + 2 * VTILE);   // 143,360

    cudaFuncSetAttribute(proj_kernel,   cudaFuncAttributeMaxDynamicSharedMemorySize, smem1);
    cudaFuncSetAttribute(scores_kernel, cudaFuncAttributeMaxDynamicSharedMemorySize, smemS);
    cudaFuncSetAttribute(av_kernel,     cudaFuncAttributeMaxDynamicSharedMemorySize, smemA);

    proj_kernel<<<dim3(17, Bb * Hh, 3), 256, smem1>>>(x, Qw, Kw, Vw);
    scores_kernel<<<dim3(81, Bb * Hh), 256, smemS>>>(atten);
    softmax_kernel<<<Bb * Hh * Ss, 128>>>(atten);
    av_kernel<<<dim3(9, Bb * Hh), 256, smemA>>>();
    outproj_kernel<<<129, 256>>>(Wm, bias, out);
}

// round 5
// speedup vs baseline: 1.6522x; 1.0480x over previous
#include <cuda_runtime.h>
#include <cuda_fp16.h>

#define Bb 8
#define Hh 9
#define Ee 128
#define Ss 1025
#define SPAD 1152   // padded sequence (rows/cols >=1025 stay zero-initialized)
#define HE 1152
#define ROWP 8320   // padded out-proj row count (65*128)
#define CP 40       // fp16 pitch for [128 x 32] k-chunk tiles
#define CTILE 10240 // 128*40*2 bytes
#define VP 136      // fp16 pitch for [32 x 128] V chunk tiles
#define VTILE32 8704 // 32*136*2 bytes
#define OAP 72      // outproj pitch for k64 tiles
#define OATILE 9216  // 64*72*2
#define OBTILE 18432 // 128*72*2

typedef unsigned long long ull;
typedef unsigned int u32;

// ---------------- scratch (zero-initialized BSS; padding never written) ------
__device__ __half g_q0[72 * SPAD * 128], g_q1[72 * SPAD * 128];
__device__ __half g_k0[72 * SPAD * 128], g_k1[72 * SPAD * 128];
__device__ __half g_v0[72 * SPAD * 128], g_v1[72 * SPAD * 128];
__device__ __half g_p0[(size_t)72 * SPAD * SPAD], g_p1[(size_t)72 * SPAD * SPAD];
__device__ __half g_h0[ROWP * HE], g_h1[ROWP * HE];
__device__ __half g_w0[Ee * HE], g_w1[Ee * HE];

// ---------------- f32x2 helpers ----------------
__device__ __forceinline__ ull fdup(float v) {
    unsigned u = __float_as_uint(v);
    return ((ull)u << 32) | (ull)u;
}
__device__ __forceinline__ void ffma2(ull& d, ull a, ull b) {
    asm("fma.rn.f32x2 %0, %1, %2, %0;" : "+l"(d) : "l"(a), "l"(b));
}
__device__ __forceinline__ float f2lo(ull v) { return __uint_as_float((unsigned)v); }
__device__ __forceinline__ float f2hi(ull v) { return __uint_as_float((unsigned)(v >> 32)); }

// ---------------- async copy / mma helpers ----------------
__device__ __forceinline__ u32 s2u(const void* p) {
    u32 a;
    asm("{ .reg .u64 t; cvta.to.shared.u64 t, %1; cvt.u32.u64 %0, t; }" : "=r"(a) : "l"(p));
    return a;
}
__device__ __forceinline__ void cp16(u32 smem, const void* g) {
    asm volatile("cp.async.cg.shared.global [%0], [%1], 16;" :: "r"(smem), "l"(g));
}
__device__ __forceinline__ void cp_commit() { asm volatile("cp.async.commit_group;" ::: "memory"); }
template <int N> __device__ __forceinline__ void cp_wait() {
    asm volatile("cp.async.wait_group %0;" :: "n"(N) : "memory");
}
__device__ __forceinline__ void ldmx4(u32& a0, u32& a1, u32& a2, u32& a3, u32 addr) {
    asm volatile("ldmatrix.sync.aligned.m8n8.x4.shared.b16 {%0,%1,%2,%3}, [%4];"
                 : "=r"(a0), "=r"(a1), "=r"(a2), "=r"(a3) : "r"(addr));
}
__device__ __forceinline__ void ldmx2(u32& b0, u32& b1, u32 addr) {
    asm volatile("ldmatrix.sync.aligned.m8n8.x2.shared.b16 {%0,%1}, [%2];"
                 : "=r"(b0), "=r"(b1) : "r"(addr));
}
__device__ __forceinline__ void ldmx2t(u32& b0, u32& b1, u32 addr) {
    asm volatile("ldmatrix.sync.aligned.m8n8.x2.trans.shared.b16 {%0,%1}, [%2];"
                 : "=r"(b0), "=r"(b1) : "r"(addr));
}
__device__ __forceinline__ void mma16816(float* c, u32 a0, u32 a1, u32 a2, u32 a3,
                                         u32 b0, u32 b1) {
    asm volatile("mma.sync.aligned.m16n8k16.row.col.f32.f16.f16.f32 "
                 "{%0,%1,%2,%3}, {%4,%5,%6,%7}, {%8,%9}, {%0,%1,%2,%3};"
                 : "+f"(c[0]), "+f"(c[1]), "+f"(c[2]), "+f"(c[3])
                 : "r"(a0), "r"(a1), "r"(a2), "r"(a3), "r"(b0), "r"(b1));
}
__device__ __forceinline__ void hsplit2(float x, __half& a, __half& b) {
    a = __float2half_rn(x);
    b = __float2half_rn(x - __half2float(a));
}

// =================================================================
// Kernel 0: split W into fp16 levels
// =================================================================
__global__ __launch_bounds__(256) void wprep_kernel(const float* __restrict__ Wm)
{
    int idx = blockIdx.x * 256 + threadIdx.x;
    if (idx < Ee * HE) {
        __half a, b;
        hsplit2(Wm[idx], a, b);
        g_w0[idx] = a;
        g_w1[idx] = b;
    }
}

// =================================================================
// Kernel 1: projections (fp32 f32x2), 32-row tiles (2 CTA/SM), fp16 split2 out
// =================================================================
__global__ __launch_bounds__(256) void proj_kernel(
    const float* __restrict__ x, const float* __restrict__ Qw,
    const float* __restrict__ Kw, const float* __restrict__ Vw)
{
    extern __shared__ unsigned char sm1[];
    ull*   xsd = (ull*)sm1;                      // [32][129] duplicated pairs
    float* ws  = (float*)(sm1 + 32 * 129 * 8);   // [128][132]

    const int tid = threadIdx.x;
    const int s0  = blockIdx.x * 32;
    const int bh  = blockIdx.y;
    const int z   = blockIdx.z;
    const int h   = bh % Hh;
    const int b   = bh / Hh;

    const float* Wm = (z == 0) ? Qw : (z == 1) ? Kw : Vw;

    #pragma unroll
    for (int it = 0; it < 16; ++it) {
        int idx = tid + it * 256;
        int e = idx >> 5, i = idx & 31;
        int s = s0 + i;
        float v = (s < Ss) ? x[((size_t)b * Ee + e) * Ss + s] : 0.f;
        xsd[i * 129 + e] = fdup(v);
    }
    const float* Wh = Wm + (size_t)h * Ee * Ee;
    #pragma unroll
    for (int it = 0; it < 64; ++it) {
        int idx = tid + it * 256;
        int kk = idx >> 7, f = idx & 127;
        ws[kk * 132 + f] = Wh[idx];
    }
    __syncthreads();

    const int rg = tid >> 4, cg = tid & 15;
    ull acc[2][4];
    #pragma unroll
    for (int j = 0; j < 2; ++j)
        #pragma unroll
        for (int c = 0; c < 4; ++c) acc[j][c] = 0ull;

    #pragma unroll 4
    for (int kk = 0; kk < 128; ++kk) {
        ulonglong2 w0 = *(const ulonglong2*)&ws[kk * 132 + cg * 8];
        ulonglong2 w1 = *(const ulonglong2*)&ws[kk * 132 + cg * 8 + 4];
        #pragma unroll
        for (int j = 0; j < 2; ++j) {
            ull a = xsd[(rg * 2 + j) * 129 + kk];
            ffma2(acc[j][0], a, w0.x);
            ffma2(acc[j][1], a, w0.y);
            ffma2(acc[j][2], a, w1.x);
            ffma2(acc[j][3], a, w1.y);
        }
    }

    __half* d0 = (z == 0) ? g_q0 : (z == 1) ? g_k0 : g_v0;
    __half* d1 = (z == 0) ? g_q1 : (z == 1) ? g_k1 : g_v1;

    #pragma unroll
    for (int j = 0; j < 2; ++j) {
        int s = s0 + rg * 2 + j;
        if (s >= Ss) continue;
        float vals[8];
        vals[0] = f2lo(acc[j][0]); vals[1] = f2hi(acc[j][0]);
        vals[2] = f2lo(acc[j][1]); vals[3] = f2hi(acc[j][1]);
        vals[4] = f2lo(acc[j][2]); vals[5] = f2hi(acc[j][2]);
        vals[6] = f2lo(acc[j][3]); vals[7] = f2hi(acc[j][3]);
        union { uint4 u; __half hh[8]; } p0, p1;
        #pragma unroll
        for (int c = 0; c < 8; ++c) hsplit2(vals[c], p0.hh[c], p1.hh[c]);
        size_t base = ((size_t)bh * SPAD + s) * 128 + cg * 8;
        *(uint4*)&d0[base] = p0.u;
        *(uint4*)&d1[base] = p1.u;
    }
}

// =================================================================
// Kernel 2: scores. fp16 GEMM, 2-way split (3 products), 4 k32 chunks,
// double-buffered. Grid (81, 72), 256 thr. smem 2 x 4 x CTILE = 81,920 B
// =================================================================
__global__ __launch_bounds__(256) void scores_kernel(float* __restrict__ atten)
{
    extern __shared__ __align__(16) unsigned char sm[];
    const u32 sbase = s2u(sm);
    const int tid = threadIdx.x, wid = tid >> 5, lane = tid & 31;
    const int m0 = (blockIdx.x / 9) * 128, n0r = (blockIdx.x % 9) * 128;
    const int bh = blockIdx.y;
    const int wr = wid >> 2, wc = wid & 3;
    const int l15 = lane & 15;
    const int STG = 4 * CTILE;

    auto load_chunk = [&](int st, int kc) {
        const int e0 = kc * 32;
        for (int i = tid; i < 2048; i += 256) {
            int t = i >> 9, rc = i & 511, r = rc >> 2, c = rc & 3;
            const __half* src = (t == 0) ? g_q0 : (t == 1) ? g_q1 : (t == 2) ? g_k0 : g_k1;
            int row0 = (t < 2) ? m0 : n0r;
            cp16(sbase + st * STG + t * CTILE + (r * CP + c * 8) * 2,
                 src + ((size_t)bh * SPAD + row0 + r) * 128 + e0 + c * 8);
        }
        cp_commit();
    };

    float acc[4][4][4];
    #pragma unroll
    for (int mt = 0; mt < 4; ++mt)
        #pragma unroll
        for (int nt = 0; nt < 4; ++nt)
            #pragma unroll
            for (int i = 0; i < 4; ++i) acc[mt][nt][i] = 0.f;

    load_chunk(0, 0);
    for (int kc = 0; kc < 4; ++kc) {
        if (kc + 1 < 4) load_chunk((kc + 1) & 1, kc + 1);
        if (kc + 1 < 4) cp_wait<1>(); else cp_wait<0>();
        __syncthreads();
        const u32 st = sbase + (kc & 1) * STG;
        const int PA[3] = {0, 0, 1};
        const int PB[3] = {0, 1, 0};
        #pragma unroll
        for (int l = 0; l < 3; ++l) {
            u32 abase = st + PA[l] * CTILE;
            u32 bbase = st + (2 + PB[l]) * CTILE;
            #pragma unroll
            for (int k = 0; k < 2; ++k) {
                const int k0 = k * 16;
                u32 bfrag[4][2];
                u32 brow = bbase + ((wc * 32 + (l15 & 7)) * CP + k0 + ((l15 >> 3) * 8)) * 2;
                #pragma unroll
                for (int nt = 0; nt < 4; ++nt)
                    ldmx2(bfrag[nt][0], bfrag[nt][1], brow + (nt * 8 * CP) * 2);
                u32 arow = abase + ((wr * 64 + l15) * CP + k0 + ((lane >> 4) * 8)) * 2;
                #pragma unroll
                for (int mt = 0; mt < 4; ++mt) {
                    u32 a0, a1, a2, a3;
                    ldmx4(a0, a1, a2, a3, arow + (mt * 16 * CP) * 2);
                    #pragma unroll
                    for (int nt = 0; nt < 4; ++nt)
                        mma16816(acc[mt][nt], a0, a1, a2, a3, bfrag[nt][0], bfrag[nt][1]);
                }
            }
        }
        __syncthreads();
    }

    // epilogue: regs -> stage smem -> coalesced gmem (scaled)
    float* stage = (float*)sm;   // [128][130]
    {
        int row = wr * 64 + (lane >> 2);
        int col = wc * 32 + (lane & 3) * 2;
        #pragma unroll
        for (int mt = 0; mt < 4; ++mt)
            #pragma unroll
            for (int nt = 0; nt < 4; ++nt) {
                float* c = acc[mt][nt];
                int rr = row + mt * 16, cc = col + nt * 8;
                *(float2*)&stage[rr * 130 + cc]       = make_float2(c[0], c[1]);
                *(float2*)&stage[(rr + 8) * 130 + cc] = make_float2(c[2], c[3]);
            }
    }
    __syncthreads();
    const float scl = 0.08838834764831845f;  // 1/sqrt(128)
    for (int idx = tid; idx < 128 * 128; idx += 256) {
        int rr = idx >> 7, c = idx & 127;
        int s = m0 + rr, t = n0r + c;
        if (s < Ss && t < Ss)
            atten[((size_t)bh * Ss + s) * Ss + t] = stage[rr * 130 + c] * scl;
    }
}

// =================================================================
// Kernel 3: softmax per row; writes fp32 atten AND fp16 2-way split of P.
// =================================================================
__global__ __launch_bounds__(128) void softmax_kernel(float* __restrict__ atten)
{
    __shared__ float buf[Ss];
    __shared__ float redm[4], reds[4];
    const int tid = threadIdx.x, wid = tid >> 5, lid = tid & 31;
    const int row = blockIdx.x;
    const int bh = row / Ss, s = row % Ss;
    float* p = atten + (size_t)row * Ss;

    float m = -3.0e38f;
    for (int c = tid; c < Ss; c += 128) { float v = p[c]; buf[c] = v; m = fmaxf(m, v); }
    #pragma unroll
    for (int o = 16; o; o >>= 1) m = fmaxf(m, __shfl_xor_sync(0xffffffffu, m, o));
    if (lid == 0) redm[wid] = m;
    __syncthreads();
    m = fmaxf(fmaxf(redm[0], redm[1]), fmaxf(redm[2], redm[3]));

    float sum = 0.f;
    for (int c = tid; c < Ss; c += 128) { float e = __expf(buf[c] - m); buf[c] = e; sum += e; }
    #pragma unroll
    for (int o = 16; o; o >>= 1) sum += __shfl_xor_sync(0xffffffffu, sum, o);
    if (lid == 0) reds[wid] = sum;
    __syncthreads();
    float inv = 1.f / (reds[0] + reds[1] + reds[2] + reds[3]);

    size_t pbase = ((size_t)bh * SPAD + s) * SPAD;
    for (int c = tid; c < Ss; c += 128) {
        float pr = buf[c] * inv;
        p[c] = pr;
        __half a, b;
        hsplit2(pr, a, b);
        g_p0[pbase + c] = a;
        g_p1[pbase + c] = b;
    }
}

// =================================================================
// Kernel 4: AV. fp16 2-way split (3 products), 36 k32 chunks, double-
// buffered, V via ldmatrix.trans. Grid (9, 72), 256 thr. smem 75,776 B.
// Emits ho fp16 split2.
// =================================================================
__global__ __launch_bounds__(256) void av_kernel()
{
    extern __shared__ __align__(16) unsigned char sm[];
    const u32 sbase = s2u(sm);
    const int tid = threadIdx.x, wid = tid >> 5, lane = tid & 31;
    const int m0 = blockIdx.x * 128;
    const int bh = blockIdx.y;
    const int b = bh / Hh, h = bh % Hh;
    const int wr = wid >> 2, wc = wid & 3;
    const int l15 = lane & 15;
    const int STG = 2 * CTILE + 2 * VTILE32;   // 37,888

    auto load_chunk = [&](int st, int ck) {
        const int t0 = ck * 32;
        for (int i = tid; i < 2048; i += 256) {
            if (i < 1024) {
                int t = i >> 9, rc = i & 511, r = rc >> 2, c = rc & 3;
                const __half* g = (t ? g_p1 : g_p0) +
                    ((size_t)bh * SPAD + m0 + r) * SPAD + t0 + c * 8;
                cp16(sbase + st * STG + t * CTILE + (r * CP + c * 8) * 2, g);
            } else {
                int j = i - 1024;
                int t = j >> 9, rc = j & 511, r = rc >> 4, c = rc & 15;
                const __half* g = (t ? g_v1 : g_v0) +
                    ((size_t)bh * SPAD + t0 + r) * 128 + c * 8;
                cp16(sbase + st * STG + 2 * CTILE + t * VTILE32 + (r * VP + c * 8) * 2, g);
            }
        }
        cp_commit();
    };

    float acc[4][4][4];
    #pragma unroll
    for (int mt = 0; mt < 4; ++mt)
        #pragma unroll
        for (int nt = 0; nt < 4; ++nt)
            #pragma unroll
            for (int i = 0; i < 4; ++i) acc[mt][nt][i] = 0.f;

    load_chunk(0, 0);
    for (int ck = 0; ck < 36; ++ck) {
        if (ck + 1 < 36) load_chunk((ck + 1) & 1, ck + 1);
        if (ck + 1 < 36) cp_wait<1>(); else cp_wait<0>();
        __syncthreads();

        const u32 st = sbase + (ck & 1) * STG;
        const int PA[3] = {0, 0, 1};
        const int PB[3] = {0, 1, 0};
        #pragma unroll
        for (int l = 0; l < 3; ++l) {
            u32 abase = st + PA[l] * CTILE;
            u32 vbase = st + 2 * CTILE + PB[l] * VTILE32;
            #pragma unroll
            for (int k = 0; k < 2; ++k) {
                const int k0 = k * 16;
                u32 bfrag[4][2];
                u32 brow = vbase + ((k0 + l15) * VP) * 2;
                #pragma unroll
                for (int nt = 0; nt < 4; ++nt)
                    ldmx2t(bfrag[nt][0], bfrag[nt][1], brow + (wc * 32 + nt * 8) * 2);
                u32 arow = abase + ((wr * 64 + l15) * CP + k0 + ((lane >> 4) * 8)) * 2;
                #pragma unroll
                for (int mt = 0; mt < 4; ++mt) {
                    u32 a0, a1, a2, a3;
                    ldmx4(a0, a1, a2, a3, arow + (mt * 16 * CP) * 2);
                    #pragma unroll
                    for (int nt = 0; nt < 4; ++nt)
                        mma16816(acc[mt][nt], a0, a1, a2, a3, bfrag[nt][0], bfrag[nt][1]);
                }
            }
        }
        __syncthreads();
    }

    // epilogue: regs -> stage -> ho fp16 splits (uint4 coalesced)
    float* stage = (float*)sm;   // [128][130]
    {
        int row = wr * 64 + (lane >> 2);
        int col = wc * 32 + (lane & 3) * 2;
        #pragma unroll
        for (int mt = 0; mt < 4; ++mt)
            #pragma unroll
            for (int nt = 0; nt < 4; ++nt) {
                float* c = acc[mt][nt];
                int rr = row + mt * 16, cc = col + nt * 8;
                *(float2*)&stage[rr * 130 + cc]       = make_float2(c[0], c[1]);
                *(float2*)&stage[(rr + 8) * 130 + cc] = make_float2(c[2], c[3]);
            }
    }
    __syncthreads();
    for (int idx = tid; idx < 128 * 16; idx += 256) {
        int rr = idx >> 4, c8 = (idx & 15) * 8;
        int s = m0 + rr;
        if (s < Ss) {
            union { uint4 u; __half hh[8]; } h0, h1;
            #pragma unroll
            for (int c = 0; c < 8; ++c)
                hsplit2(stage[rr * 130 + c8 + c], h0.hh[c], h1.hh[c]);
            size_t base = ((size_t)b * Ss + s) * HE + h * Ee + c8;
            *(uint4*)&g_h0[base] = h0.u;
            *(uint4*)&g_h1[base] = h1.u;
        }
    }
}

// =================================================================
// Kernel 5: outproj via fp16 HMMA (3 products), 18 k64 chunks.
// Tile 64 rows x 128 e. Grid 130, 256 thr. smem 110,592 B.
// =================================================================
__global__ __launch_bounds__(256) void outproj_kernel(
    const float* __restrict__ bias, float* __restrict__ out)
{
    extern __shared__ __align__(16) unsigned char sm[];
    const u32 sbase = s2u(sm);
    const int tid = threadIdx.x, wid = tid >> 5, lane = tid & 31;
    const int row0 = blockIdx.x * 64;
    const int wr = wid >> 2, wc = wid & 3;
    const int l15 = lane & 15;
    const int STG = 2 * OATILE + 2 * OBTILE;   // 55,296

    auto load_chunk = [&](int st, int ck) {
        const int k0g = ck * 64;
        for (int i = tid; i < 3072; i += 256) {
            if (i < 1024) {
                int t = i >> 9, rc = i & 511, r = rc >> 3, c = rc & 7;
                const __half* g = (t ? g_h1 : g_h0) + (size_t)(row0 + r) * HE + k0g + c * 8;
                cp16(sbase + st * STG + t * OATILE + (r * OAP + c * 8) * 2, g);
            } else {
                int j = i - 1024;
                int t = j >> 10, rc = j & 1023, r = rc >> 3, c = rc & 7;
                const __half* g = (t ? g_w1 : g_w0) + (size_t)r * HE + k0g + c * 8;
                cp16(sbase + st * STG + 2 * OATILE + t * OBTILE + (r * OAP + c * 8) * 2, g);
            }
        }
        cp_commit();
    };

    float acc[2][4][4];
    #pragma unroll
    for (int mt = 0; mt < 2; ++mt)
        #pragma unroll
        for (int nt = 0; nt < 4; ++nt)
            #pragma unroll
            for (int i = 0; i < 4; ++i) acc[mt][nt][i] = 0.f;

    load_chunk(0, 0);
    for (int ck = 0; ck < 18; ++ck) {
        if (ck + 1 < 18) load_chunk((ck + 1) & 1, ck + 1);
        if (ck + 1 < 18) cp_wait<1>(); else cp_wait<0>();
        __syncthreads();

        const u32 st = sbase + (ck & 1) * STG;
        const int PA[3] = {0, 0, 1};
        const int PB[3] = {0, 1, 0};
        #pragma unroll
        for (int l = 0; l < 3; ++l) {
            u32 abase = st + PA[l] * OATILE;
            u32 bbase = st + 2 * OATILE + PB[l] * OBTILE;
            #pragma unroll
            for (int k = 0; k < 4; ++k) {
                const int k0 = k * 16;
                u32 bfrag[4][2];
                u32 brow = bbase + ((wc * 32 + (l15 & 7)) * OAP + k0 + ((l15 >> 3) * 8)) * 2;
                #pragma unroll
                for (int nt = 0; nt < 4; ++nt)
                    ldmx2(bfrag[nt][0], bfrag[nt][1], brow + (nt * 8 * OAP) * 2);
                u32 arow = abase + ((wr * 32 + l15) * OAP + k0 + ((lane >> 4) * 8)) * 2;
                #pragma unroll
                for (int mt = 0; mt < 2; ++mt) {
                    u32 a0, a1, a2, a3;
                    ldmx4(a0, a1, a2, a3, arow + (mt * 16 * OAP) * 2);
                    #pragma unroll
                    for (int nt = 0; nt < 4; ++nt)
                        mma16816(acc[mt][nt], a0, a1, a2, a3, bfrag[nt][0], bfrag[nt][1]);
                }
            }
        }
        __syncthreads();
    }

    // epilogue: regs -> stage [64][129] -> transposed coalesced stores
    float* stage = (float*)sm;
    {
        int row = wr * 32 + (lane >> 2);
        int col = wc * 32 + (lane & 3) * 2;
        #pragma unroll
        for (int mt = 0; mt < 2; ++mt)
            #pragma unroll
            for (int nt = 0; nt < 4; ++nt) {
                float* c = acc[mt][nt];
                int rr = row + mt * 16, cc = col + nt * 8;
                stage[rr * 129 + cc]           = c[0];
                stage[rr * 129 + cc + 1]       = c[1];
                stage[(rr + 8) * 129 + cc]     = c[2];
                stage[(rr + 8) * 129 + cc + 1] = c[3];
            }
    }
    __syncthreads();
    for (int idx = tid; idx < 128 * 64; idx += 256) {
        int e = idx >> 6, rr = idx & 63;
        int rg = row0 + rr;
        if (rg < Bb * Ss) {
            int b = rg / Ss, s = rg % Ss;
            out[((size_t)b * Ee + e) * Ss + s] = stage[rr * 129 + e] + bias[e];
        }
    }
}

// =================================================================
extern "C" void kernel_launch(void* const* d_in, const int* in_sizes, int n_in,
                              void* d_out, int out_size)
{
    const float* x    = (const float*)d_in[0];
    const float* Qw   = (const float*)d_in[1];
    const float* Kw   = (const float*)d_in[2];
    const float* Vw   = (const float*)d_in[3];
    const float* Wm   = (const float*)d_in[4];
    const float* bias = (const float*)d_in[5];

    float* out   = (float*)d_out;                    // [B,E,S]
    float* atten = out + (size_t)Bb * Ee * Ss;       // [B,H,S,S]

    const int smem1 = 32 * 129 * 8 + 128 * 132 * 4;  // 100,608
    const int smemS = 2 * 4 * CTILE;                 // 81,920
    const int smemA = 2 * (2 * CTILE + 2 * VTILE32); // 75,776
    const int smemO = 2 * (2 * OATILE + 2 * OBTILE); // 110,592

    cudaFuncSetAttribute(proj_kernel,    cudaFuncAttributeMaxDynamicSharedMemorySize, smem1);
    cudaFuncSetAttribute(scores_kernel,  cudaFuncAttributeMaxDynamicSharedMemorySize, smemS);
    cudaFuncSetAttribute(av_kernel,      cudaFuncAttributeMaxDynamicSharedMemorySize, smemA);
    cudaFuncSetAttribute(outproj_kernel, cudaFuncAttributeMaxDynamicSharedMemorySize, smemO);

    wprep_kernel<<<576, 256>>>(Wm);
    proj_kernel<<<dim3(33, Bb * Hh, 3), 256, smem1>>>(x, Qw, Kw, Vw);
    scores_kernel<<<dim3(81, Bb * Hh), 256, smemS>>>(atten);
    softmax_kernel<<<Bb * Hh * Ss, 128>>>(atten);
    av_kernel<<<dim3(9, Bb * Hh), 256, smemA>>>();
    outproj_kernel<<<130, 256, smemO>>>(bias, out);
}

// round 6
// speedup vs baseline: 2.2137x; 1.3399x over previous
#include <cuda_runtime.h>
#include <cuda_fp16.h>

#define Bb 8
#define Hh 9
#define Ee 128
#define Ss 1025
#define SPAD 1152   // padded sequence (rows/cols >=1025 stay zero-initialized)
#define HE 1152
#define ROWP 8320   // padded out-proj row count (65*128)
#define CP 40       // fp16 pitch for [128 x 32] k-chunk tiles
#define CTILE 10240 // 128*40*2 bytes
#define VP 136      // fp16 pitch for [32 x 128] B-trans chunk tiles
#define VTILE32 8704 // 32*136*2 bytes
#define OAP 72      // outproj pitch for k64 tiles
#define OATILE 9216  // 64*72*2
#define OBTILE 18432 // 128*72*2

typedef unsigned long long ull;
typedef unsigned int u32;

// ---------------- scratch (zero-initialized BSS; padding never written) ------
__device__ __half g_x0[Bb * SPAD * 128], g_x1[Bb * SPAD * 128];
__device__ __half g_wq0[Hh * Ee * Ee], g_wq1[Hh * Ee * Ee];
__device__ __half g_wk0[Hh * Ee * Ee], g_wk1[Hh * Ee * Ee];
__device__ __half g_wv0[Hh * Ee * Ee], g_wv1[Hh * Ee * Ee];
__device__ __half g_q0[72 * SPAD * 128], g_q1[72 * SPAD * 128];
__device__ __half g_k0[72 * SPAD * 128], g_k1[72 * SPAD * 128];
__device__ __half g_v0[72 * SPAD * 128], g_v1[72 * SPAD * 128];
__device__ __half g_p0[(size_t)72 * SPAD * SPAD], g_p1[(size_t)72 * SPAD * SPAD];
__device__ __half g_h0[ROWP * HE], g_h1[ROWP * HE];
__device__ __half g_w0[Ee * HE], g_w1[Ee * HE];

// ---------------- async copy / mma helpers ----------------
__device__ __forceinline__ u32 s2u(const void* p) {
    u32 a;
    asm("{ .reg .u64 t; cvta.to.shared.u64 t, %1; cvt.u32.u64 %0, t; }" : "=r"(a) : "l"(p));
    return a;
}
__device__ __forceinline__ void cp16(u32 smem, const void* g) {
    asm volatile("cp.async.cg.shared.global [%0], [%1], 16;" :: "r"(smem), "l"(g));
}
__device__ __forceinline__ void cp_commit() { asm volatile("cp.async.commit_group;" ::: "memory"); }
template <int N> __device__ __forceinline__ void cp_wait() {
    asm volatile("cp.async.wait_group %0;" :: "n"(N) : "memory");
}
__device__ __forceinline__ void ldmx4(u32& a0, u32& a1, u32& a2, u32& a3, u32 addr) {
    asm volatile("ldmatrix.sync.aligned.m8n8.x4.shared.b16 {%0,%1,%2,%3}, [%4];"
                 : "=r"(a0), "=r"(a1), "=r"(a2), "=r"(a3) : "r"(addr));
}
__device__ __forceinline__ void ldmx2(u32& b0, u32& b1, u32 addr) {
    asm volatile("ldmatrix.sync.aligned.m8n8.x2.shared.b16 {%0,%1}, [%2];"
                 : "=r"(b0), "=r"(b1) : "r"(addr));
}
__device__ __forceinline__ void ldmx2t(u32& b0, u32& b1, u32 addr) {
    asm volatile("ldmatrix.sync.aligned.m8n8.x2.trans.shared.b16 {%0,%1}, [%2];"
                 : "=r"(b0), "=r"(b1) : "r"(addr));
}
__device__ __forceinline__ void mma16816(float* c, u32 a0, u32 a1, u32 a2, u32 a3,
                                         u32 b0, u32 b1) {
    asm volatile("mma.sync.aligned.m16n8k16.row.col.f32.f16.f16.f32 "
                 "{%0,%1,%2,%3}, {%4,%5,%6,%7}, {%8,%9}, {%0,%1,%2,%3};"
                 : "+f"(c[0]), "+f"(c[1]), "+f"(c[2]), "+f"(c[3])
                 : "r"(a0), "r"(a1), "r"(a2), "r"(a3), "r"(b0), "r"(b1));
}
__device__ __forceinline__ void hsplit2(float x, __half& a, __half& b) {
    a = __float2half_rn(x);
    b = __float2half_rn(x - __half2float(a));
}

// =================================================================
// Kernel 0a: split W into fp16 levels
// =================================================================
__global__ __launch_bounds__(256) void wprep_kernel(const float* __restrict__ Wm)
{
    int idx = blockIdx.x * 256 + threadIdx.x;
    if (idx < Ee * HE) {
        __half a, b;
        hsplit2(Wm[idx], a, b);
        g_w0[idx] = a;
        g_w1[idx] = b;
    }
}

// =================================================================
// Kernel 0b: split Q/K/V weight matrices into fp16 levels (natural [h][e][f])
// =================================================================
__global__ __launch_bounds__(256) void qkvprep_kernel(
    const float* __restrict__ Qw, const float* __restrict__ Kw,
    const float* __restrict__ Vw)
{
    int idx = blockIdx.x * 256 + threadIdx.x;
    const int N = Hh * Ee * Ee;
    if (idx < 3 * N) {
        int z = idx / N, j = idx % N;
        const float* src = (z == 0) ? Qw : (z == 1) ? Kw : Vw;
        __half* d0 = (z == 0) ? g_wq0 : (z == 1) ? g_wk0 : g_wv0;
        __half* d1 = (z == 0) ? g_wq1 : (z == 1) ? g_wk1 : g_wv1;
        __half a, b;
        hsplit2(src[j], a, b);
        d0[j] = a;
        d1[j] = b;
    }
}

// =================================================================
// Kernel 0c: transpose x [B,E,S] -> xt splits [b][s][e] fp16 x2
// grid (17, 8): 64 s-rows x 128 e per block
// =================================================================
__global__ __launch_bounds__(256) void xprep_kernel(const float* __restrict__ x)
{
    __shared__ float ts[128 * 65];
    const int tid = threadIdx.x;
    const int s0 = blockIdx.x * 64;
    const int b = blockIdx.y;

    #pragma unroll
    for (int it = 0; it < 32; ++it) {
        int idx = tid + it * 256;
        int e = idx >> 6, sl = idx & 63;
        int s = s0 + sl;
        ts[e * 65 + sl] = (s < Ss) ? x[((size_t)b * Ee + e) * Ss + s] : 0.f;
    }
    __syncthreads();
    #pragma unroll
    for (int it = 0; it < 32; ++it) {
        int idx = tid + it * 256;
        int sl = idx >> 7, e = idx & 127;
        int s = s0 + sl;
        if (s < Ss) {
            __half a, bb;
            hsplit2(ts[e * 65 + sl], a, bb);
            size_t o = ((size_t)b * SPAD + s) * 128 + e;
            g_x0[o] = a;
            g_x1[o] = bb;
        }
    }
}

// =================================================================
// Kernel 1: projections via fp16 HMMA (3 products), 4 k32 chunks.
// Grid (9, 8, 27): mtile, b, (h*3+zt). Emits q/k/v fp16 split2.
// =================================================================
__global__ __launch_bounds__(256) void proj_kernel()
{
    extern __shared__ __align__(16) unsigned char sm[];
    const u32 sbase = s2u(sm);
    const int tid = threadIdx.x, wid = tid >> 5, lane = tid & 31;
    const int m0 = blockIdx.x * 128;
    const int b = blockIdx.y;
    const int zt = blockIdx.z % 3, h = blockIdx.z / 3;
    const int wr = wid >> 2, wc = wid & 3;
    const int l15 = lane & 15;
    const int STG = 2 * CTILE + 2 * VTILE32;   // 37,888

    const __half* w0 = (zt == 0) ? g_wq0 : (zt == 1) ? g_wk0 : g_wv0;
    const __half* w1 = (zt == 0) ? g_wq1 : (zt == 1) ? g_wk1 : g_wv1;

    auto load_chunk = [&](int st, int ck) {
        const int e0 = ck * 32;
        for (int i = tid; i < 2048; i += 256) {
            if (i < 1024) {
                int t = i >> 9, rc = i & 511, r = rc >> 2, c = rc & 3;
                const __half* g = (t ? g_x1 : g_x0) +
                    ((size_t)b * SPAD + m0 + r) * 128 + e0 + c * 8;
                cp16(sbase + st * STG + t * CTILE + (r * CP + c * 8) * 2, g);
            } else {
                int j = i - 1024;
                int t = j >> 9, rc = j & 511, r = rc >> 4, c = rc & 15;
                const __half* g = (t ? w1 : w0) + ((size_t)h * 128 + e0 + r) * 128 + c * 8;
                cp16(sbase + st * STG + 2 * CTILE + t * VTILE32 + (r * VP + c * 8) * 2, g);
            }
        }
        cp_commit();
    };

    float acc[4][4][4];
    #pragma unroll
    for (int mt = 0; mt < 4; ++mt)
        #pragma unroll
        for (int nt = 0; nt < 4; ++nt)
            #pragma unroll
            for (int i = 0; i < 4; ++i) acc[mt][nt][i] = 0.f;

    load_chunk(0, 0);
    for (int ck = 0; ck < 4; ++ck) {
        if (ck + 1 < 4) load_chunk((ck + 1) & 1, ck + 1);
        if (ck + 1 < 4) cp_wait<1>(); else cp_wait<0>();
        __syncthreads();

        const u32 st = sbase + (ck & 1) * STG;
        const int PA[3] = {0, 0, 1};
        const int PB[3] = {0, 1, 0};
        #pragma unroll
        for (int l = 0; l < 3; ++l) {
            u32 abase = st + PA[l] * CTILE;
            u32 vbase = st + 2 * CTILE + PB[l] * VTILE32;
            #pragma unroll
            for (int k = 0; k < 2; ++k) {
                const int k0 = k * 16;
                u32 bfrag[4][2];
                u32 brow = vbase + ((k0 + l15) * VP) * 2;
                #pragma unroll
                for (int nt = 0; nt < 4; ++nt)
                    ldmx2t(bfrag[nt][0], bfrag[nt][1], brow + (wc * 32 + nt * 8) * 2);
                u32 arow = abase + ((wr * 64 + l15) * CP + k0 + ((lane >> 4) * 8)) * 2;
                #pragma unroll
                for (int mt = 0; mt < 4; ++mt) {
                    u32 a0, a1, a2, a3;
                    ldmx4(a0, a1, a2, a3, arow + (mt * 16 * CP) * 2);
                    #pragma unroll
                    for (int nt = 0; nt < 4; ++nt)
                        mma16816(acc[mt][nt], a0, a1, a2, a3, bfrag[nt][0], bfrag[nt][1]);
                }
            }
        }
        __syncthreads();
    }

    // epilogue: regs -> stage -> q/k/v fp16 splits
    float* stage = (float*)sm;   // [128][130]
    {
        int row = wr * 64 + (lane >> 2);
        int col = wc * 32 + (lane & 3) * 2;
        #pragma unroll
        for (int mt = 0; mt < 4; ++mt)
            #pragma unroll
            for (int nt = 0; nt < 4; ++nt) {
                float* c = acc[mt][nt];
                int rr = row + mt * 16, cc = col + nt * 8;
                *(float2*)&stage[rr * 130 + cc]       = make_float2(c[0], c[1]);
                *(float2*)&stage[(rr + 8) * 130 + cc] = make_float2(c[2], c[3]);
            }
    }
    __syncthreads();
    __half* d0 = (zt == 0) ? g_q0 : (zt == 1) ? g_k0 : g_v0;
    __half* d1 = (zt == 0) ? g_q1 : (zt == 1) ? g_k1 : g_v1;
    const int bh = b * Hh + h;
    for (int idx = tid; idx < 128 * 16; idx += 256) {
        int rr = idx >> 4, c8 = (idx & 15) * 8;
        int s = m0 + rr;
        if (s < Ss) {
            union { uint4 u; __half hh[8]; } h0, h1;
            #pragma unroll
            for (int c = 0; c < 8; ++c)
                hsplit2(stage[rr * 130 + c8 + c], h0.hh[c], h1.hh[c]);
            size_t base = ((size_t)bh * SPAD + s) * 128 + c8;
            *(uint4*)&d0[base] = h0.u;
            *(uint4*)&d1[base] = h1.u;
        }
    }
}

// =================================================================
// Kernel 2: scores. fp16 GEMM, 2-way split (3 products), 4 k32 chunks,
// double-buffered. Grid (81, 72), 256 thr.
// =================================================================
__global__ __launch_bounds__(256) void scores_kernel(float* __restrict__ atten)
{
    extern __shared__ __align__(16) unsigned char sm[];
    const u32 sbase = s2u(sm);
    const int tid = threadIdx.x, wid = tid >> 5, lane = tid & 31;
    const int m0 = (blockIdx.x / 9) * 128, n0r = (blockIdx.x % 9) * 128;
    const int bh = blockIdx.y;
    const int wr = wid >> 2, wc = wid & 3;
    const int l15 = lane & 15;
    const int STG = 4 * CTILE;

    auto load_chunk = [&](int st, int kc) {
        const int e0 = kc * 32;
        for (int i = tid; i < 2048; i += 256) {
            int t = i >> 9, rc = i & 511, r = rc >> 2, c = rc & 3;
            const __half* src = (t == 0) ? g_q0 : (t == 1) ? g_q1 : (t == 2) ? g_k0 : g_k1;
            int row0 = (t < 2) ? m0 : n0r;
            cp16(sbase + st * STG + t * CTILE + (r * CP + c * 8) * 2,
                 src + ((size_t)bh * SPAD + row0 + r) * 128 + e0 + c * 8);
        }
        cp_commit();
    };

    float acc[4][4][4];
    #pragma unroll
    for (int mt = 0; mt < 4; ++mt)
        #pragma unroll
        for (int nt = 0; nt < 4; ++nt)
            #pragma unroll
            for (int i = 0; i < 4; ++i) acc[mt][nt][i] = 0.f;

    load_chunk(0, 0);
    for (int kc = 0; kc < 4; ++kc) {
        if (kc + 1 < 4) load_chunk((kc + 1) & 1, kc + 1);
        if (kc + 1 < 4) cp_wait<1>(); else cp_wait<0>();
        __syncthreads();
        const u32 st = sbase + (kc & 1) * STG;
        const int PA[3] = {0, 0, 1};
        const int PB[3] = {0, 1, 0};
        #pragma unroll
        for (int l = 0; l < 3; ++l) {
            u32 abase = st + PA[l] * CTILE;
            u32 bbase = st + (2 + PB[l]) * CTILE;
            #pragma unroll
            for (int k = 0; k < 2; ++k) {
                const int k0 = k * 16;
                u32 bfrag[4][2];
                u32 brow = bbase + ((wc * 32 + (l15 & 7)) * CP + k0 + ((l15 >> 3) * 8)) * 2;
                #pragma unroll
                for (int nt = 0; nt < 4; ++nt)
                    ldmx2(bfrag[nt][0], bfrag[nt][1], brow + (nt * 8 * CP) * 2);
                u32 arow = abase + ((wr * 64 + l15) * CP + k0 + ((lane >> 4) * 8)) * 2;
                #pragma unroll
                for (int mt = 0; mt < 4; ++mt) {
                    u32 a0, a1, a2, a3;
                    ldmx4(a0, a1, a2, a3, arow + (mt * 16 * CP) * 2);
                    #pragma unroll
                    for (int nt = 0; nt < 4; ++nt)
                        mma16816(acc[mt][nt], a0, a1, a2, a3, bfrag[nt][0], bfrag[nt][1]);
                }
            }
        }
        __syncthreads();
    }

    float* stage = (float*)sm;   // [128][130]
    {
        int row = wr * 64 + (lane >> 2);
        int col = wc * 32 + (lane & 3) * 2;
        #pragma unroll
        for (int mt = 0; mt < 4; ++mt)
            #pragma unroll
            for (int nt = 0; nt < 4; ++nt) {
                float* c = acc[mt][nt];
                int rr = row + mt * 16, cc = col + nt * 8;
                *(float2*)&stage[rr * 130 + cc]       = make_float2(c[0], c[1]);
                *(float2*)&stage[(rr + 8) * 130 + cc] = make_float2(c[2], c[3]);
            }
    }
    __syncthreads();
    const float scl = 0.08838834764831845f;  // 1/sqrt(128)
    for (int idx = tid; idx < 128 * 128; idx += 256) {
        int rr = idx >> 7, c = idx & 127;
        int s = m0 + rr, t = n0r + c;
        if (s < Ss && t < Ss)
            atten[((size_t)bh * Ss + s) * Ss + t] = stage[rr * 130 + c] * scl;
    }
}

// =================================================================
// Kernel 3: softmax per row; writes fp32 atten AND fp16 2-way split of P.
// =================================================================
__global__ __launch_bounds__(128) void softmax_kernel(float* __restrict__ atten)
{
    __shared__ float buf[Ss];
    __shared__ float redm[4], reds[4];
    const int tid = threadIdx.x, wid = tid >> 5, lid = tid & 31;
    const int row = blockIdx.x;
    const int bh = row / Ss, s = row % Ss;
    float* p = atten + (size_t)row * Ss;

    float m = -3.0e38f;
    for (int c = tid; c < Ss; c += 128) { float v = p[c]; buf[c] = v; m = fmaxf(m, v); }
    #pragma unroll
    for (int o = 16; o; o >>= 1) m = fmaxf(m, __shfl_xor_sync(0xffffffffu, m, o));
    if (lid == 0) redm[wid] = m;
    __syncthreads();
    m = fmaxf(fmaxf(redm[0], redm[1]), fmaxf(redm[2], redm[3]));

    float sum = 0.f;
    for (int c = tid; c < Ss; c += 128) { float e = __expf(buf[c] - m); buf[c] = e; sum += e; }
    #pragma unroll
    for (int o = 16; o; o >>= 1) sum += __shfl_xor_sync(0xffffffffu, sum, o);
    if (lid == 0) reds[wid] = sum;
    __syncthreads();
    float inv = 1.f / (reds[0] + reds[1] + reds[2] + reds[3]);

    size_t pbase = ((size_t)bh * SPAD + s) * SPAD;
    for (int c = tid; c < Ss; c += 128) {
        float pr = buf[c] * inv;
        p[c] = pr;
        __half a, b;
        hsplit2(pr, a, b);
        g_p0[pbase + c] = a;
        g_p1[pbase + c] = b;
    }
}

// =================================================================
// Kernel 4: AV. fp16 2-way split (3 products), 36 k32 chunks, double-
// buffered, V via ldmatrix.trans. Grid (9, 72), 256 thr.
// =================================================================
__global__ __launch_bounds__(256) void av_kernel()
{
    extern __shared__ __align__(16) unsigned char sm[];
    const u32 sbase = s2u(sm);
    const int tid = threadIdx.x, wid = tid >> 5, lane = tid & 31;
    const int m0 = blockIdx.x * 128;
    const int bh = blockIdx.y;
    const int b = bh / Hh, h = bh % Hh;
    const int wr = wid >> 2, wc = wid & 3;
    const int l15 = lane & 15;
    const int STG = 2 * CTILE + 2 * VTILE32;   // 37,888

    auto load_chunk = [&](int st, int ck) {
        const int t0 = ck * 32;
        for (int i = tid; i < 2048; i += 256) {
            if (i < 1024) {
                int t = i >> 9, rc = i & 511, r = rc >> 2, c = rc & 3;
                const __half* g = (t ? g_p1 : g_p0) +
                    ((size_t)bh * SPAD + m0 + r) * SPAD + t0 + c * 8;
                cp16(sbase + st * STG + t * CTILE + (r * CP + c * 8) * 2, g);
            } else {
                int j = i - 1024;
                int t = j >> 9, rc = j & 511, r = rc >> 4, c = rc & 15;
                const __half* g = (t ? g_v1 : g_v0) +
                    ((size_t)bh * SPAD + t0 + r) * 128 + c * 8;
                cp16(sbase + st * STG + 2 * CTILE + t * VTILE32 + (r * VP + c * 8) * 2, g);
            }
        }
        cp_commit();
    };

    float acc[4][4][4];
    #pragma unroll
    for (int mt = 0; mt < 4; ++mt)
        #pragma unroll
        for (int nt = 0; nt < 4; ++nt)
            #pragma unroll
            for (int i = 0; i < 4; ++i) acc[mt][nt][i] = 0.f;

    load_chunk(0, 0);
    for (int ck = 0; ck < 36; ++ck) {
        if (ck + 1 < 36) load_chunk((ck + 1) & 1, ck + 1);
        if (ck + 1 < 36) cp_wait<1>(); else cp_wait<0>();
        __syncthreads();

        const u32 st = sbase + (ck & 1) * STG;
        const int PA[3] = {0, 0, 1};
        const int PB[3] = {0, 1, 0};
        #pragma unroll
        for (int l = 0; l < 3; ++l) {
            u32 abase = st + PA[l] * CTILE;
            u32 vbase = st + 2 * CTILE + PB[l] * VTILE32;
            #pragma unroll
            for (int k = 0; k < 2; ++k) {
                const int k0 = k * 16;
                u32 bfrag[4][2];
                u32 brow = vbase + ((k0 + l15) * VP) * 2;
                #pragma unroll
                for (int nt = 0; nt < 4; ++nt)
                    ldmx2t(bfrag[nt][0], bfrag[nt][1], brow + (wc * 32 + nt * 8) * 2);
                u32 arow = abase + ((wr * 64 + l15) * CP + k0 + ((lane >> 4) * 8)) * 2;
                #pragma unroll
                for (int mt = 0; mt < 4; ++mt) {
                    u32 a0, a1, a2, a3;
                    ldmx4(a0, a1, a2, a3, arow + (mt * 16 * CP) * 2);
                    #pragma unroll
                    for (int nt = 0; nt < 4; ++nt)
                        mma16816(acc[mt][nt], a0, a1, a2, a3, bfrag[nt][0], bfrag[nt][1]);
                }
            }
        }
        __syncthreads();
    }

    float* stage = (float*)sm;   // [128][130]
    {
        int row = wr * 64 + (lane >> 2);
        int col = wc * 32 + (lane & 3) * 2;
        #pragma unroll
        for (int mt = 0; mt < 4; ++mt)
            #pragma unroll
            for (int nt = 0; nt < 4; ++nt) {
                float* c = acc[mt][nt];
                int rr = row + mt * 16, cc = col + nt * 8;
                *(float2*)&stage[rr * 130 + cc]       = make_float2(c[0], c[1]);
                *(float2*)&stage[(rr + 8) * 130 + cc] = make_float2(c[2], c[3]);
            }
    }
    __syncthreads();
    for (int idx = tid; idx < 128 * 16; idx += 256) {
        int rr = idx >> 4, c8 = (idx & 15) * 8;
        int s = m0 + rr;
        if (s < Ss) {
            union { uint4 u; __half hh[8]; } h0, h1;
            #pragma unroll
            for (int c = 0; c < 8; ++c)
                hsplit2(stage[rr * 130 + c8 + c], h0.hh[c], h1.hh[c]);
            size_t base = ((size_t)b * Ss + s) * HE + h * Ee + c8;
            *(uint4*)&g_h0[base] = h0.u;
            *(uint4*)&g_h1[base] = h1.u;
        }
    }
}

// =================================================================
// Kernel 5: outproj via fp16 HMMA (3 products), 18 k64 chunks.
// =================================================================
__global__ __launch_bounds__(256) void outproj_kernel(
    const float* __restrict__ bias, float* __restrict__ out)
{
    extern __shared__ __align__(16) unsigned char sm[];
    const u32 sbase = s2u(sm);
    const int tid = threadIdx.x, wid = tid >> 5, lane = tid & 31;
    const int row0 = blockIdx.x * 64;
    const int wr = wid >> 2, wc = wid & 3;
    const int l15 = lane & 15;
    const int STG = 2 * OATILE + 2 * OBTILE;   // 55,296

    auto load_chunk = [&](int st, int ck) {
        const int k0g = ck * 64;
        for (int i = tid; i < 3072; i += 256) {
            if (i < 1024) {
                int t = i >> 9, rc = i & 511, r = rc >> 3, c = rc & 7;
                const __half* g = (t ? g_h1 : g_h0) + (size_t)(row0 + r) * HE + k0g + c * 8;
                cp16(sbase + st * STG + t * OATILE + (r * OAP + c * 8) * 2, g);
            } else {
                int j = i - 1024;
                int t = j >> 10, rc = j & 1023, r = rc >> 3, c = rc & 7;
                const __half* g = (t ? g_w1 : g_w0) + (size_t)r * HE + k0g + c * 8;
                cp16(sbase + st * STG + 2 * OATILE + t * OBTILE + (r * OAP + c * 8) * 2, g);
            }
        }
        cp_commit();
    };

    float acc[2][4][4];
    #pragma unroll
    for (int mt = 0; mt < 2; ++mt)
        #pragma unroll
        for (int nt = 0; nt < 4; ++nt)
            #pragma unroll
            for (int i = 0; i < 4; ++i) acc[mt][nt][i] = 0.f;

    load_chunk(0, 0);
    for (int ck = 0; ck < 18; ++ck) {
        if (ck + 1 < 18) load_chunk((ck + 1) & 1, ck + 1);
        if (ck + 1 < 18) cp_wait<1>(); else cp_wait<0>();
        __syncthreads();

        const u32 st = sbase + (ck & 1) * STG;
        const int PA[3] = {0, 0, 1};
        const int PB[3] = {0, 1, 0};
        #pragma unroll
        for (int l = 0; l < 3; ++l) {
            u32 abase = st + PA[l] * OATILE;
            u32 bbase = st + 2 * OATILE + PB[l] * OBTILE;
            #pragma unroll
            for (int k = 0; k < 4; ++k) {
                const int k0 = k * 16;
                u32 bfrag[4][2];
                u32 brow = bbase + ((wc * 32 + (l15 & 7)) * OAP + k0 + ((l15 >> 3) * 8)) * 2;
                #pragma unroll
                for (int nt = 0; nt < 4; ++nt)
                    ldmx2(bfrag[nt][0], bfrag[nt][1], brow + (nt * 8 * OAP) * 2);
                u32 arow = abase + ((wr * 32 + l15) * OAP + k0 + ((lane >> 4) * 8)) * 2;
                #pragma unroll
                for (int mt = 0; mt < 2; ++mt) {
                    u32 a0, a1, a2, a3;
                    ldmx4(a0, a1, a2, a3, arow + (mt * 16 * OAP) * 2);
                    #pragma unroll
                    for (int nt = 0; nt < 4; ++nt)
                        mma16816(acc[mt][nt], a0, a1, a2, a3, bfrag[nt][0], bfrag[nt][1]);
                }
            }
        }
        __syncthreads();
    }

    float* stage = (float*)sm;
    {
        int row = wr * 32 + (lane >> 2);
        int col = wc * 32 + (lane & 3) * 2;
        #pragma unroll
        for (int mt = 0; mt < 2; ++mt)
            #pragma unroll
            for (int nt = 0; nt < 4; ++nt) {
                float* c = acc[mt][nt];
                int rr = row + mt * 16, cc = col + nt * 8;
                stage[rr * 129 + cc]           = c[0];
                stage[rr * 129 + cc + 1]       = c[1];
                stage[(rr + 8) * 129 + cc]     = c[2];
                stage[(rr + 8) * 129 + cc + 1] = c[3];
            }
    }
    __syncthreads();
    for (int idx = tid; idx < 128 * 64; idx += 256) {
        int e = idx >> 6, rr = idx & 63;
        int rg = row0 + rr;
        if (rg < Bb * Ss) {
            int b = rg / Ss, s = rg % Ss;
            out[((size_t)b * Ee + e) * Ss + s] = stage[rr * 129 + e] + bias[e];
        }
    }
}

// =================================================================
extern "C" void kernel_launch(void* const* d_in, const int* in_sizes, int n_in,
                              void* d_out, int out_size)
{
    const float* x    = (const float*)d_in[0];
    const float* Qw   = (const float*)d_in[1];
    const float* Kw   = (const float*)d_in[2];
    const float* Vw   = (const float*)d_in[3];
    const float* Wm   = (const float*)d_in[4];
    const float* bias = (const float*)d_in[5];

    float* out   = (float*)d_out;                    // [B,E,S]
    float* atten = out + (size_t)Bb * Ee * Ss;       // [B,H,S,S]

    const int smemP = 2 * (2 * CTILE + 2 * VTILE32); // 75,776
    const int smemS = 2 * 4 * CTILE;                 // 81,920
    const int smemA = 2 * (2 * CTILE + 2 * VTILE32); // 75,776
    const int smemO = 2 * (2 * OATILE + 2 * OBTILE); // 110,592

    cudaFuncSetAttribute(proj_kernel,    cudaFuncAttributeMaxDynamicSharedMemorySize, smemP);
    cudaFuncSetAttribute(scores_kernel,  cudaFuncAttributeMaxDynamicSharedMemorySize, smemS);
    cudaFuncSetAttribute(av_kernel,      cudaFuncAttributeMaxDynamicSharedMemorySize, smemA);
    cudaFuncSetAttribute(outproj_kernel, cudaFuncAttributeMaxDynamicSharedMemorySize, smemO);

    wprep_kernel<<<576, 256>>>(Wm);
    qkvprep_kernel<<<1728, 256>>>(Qw, Kw, Vw);
    xprep_kernel<<<dim3(17, Bb), 256>>>(x);
    proj_kernel<<<dim3(9, Bb, 27), 256, smemP>>>();
    scores_kernel<<<dim3(81, Bb * Hh), 256, smemS>>>(atten);
    softmax_kernel<<<Bb * Hh * Ss, 128>>>(atten);
    av_kernel<<<dim3(9, Bb * Hh), 256, smemA>>>();
    outproj_kernel<<<130, 256, smemO>>>(bias, out);
}

// round 7
// speedup vs baseline: 2.6455x; 1.1950x over previous
#include <cuda_runtime.h>
#include <cuda_fp16.h>

#define Bb 8
#define Hh 9
#define Ee 128
#define Ss 1025
#define SPAD 1152   // padded sequence (rows/cols >=1025 stay zero-initialized)
#define HE 1152
#define ROWP 8320   // padded out-proj row count (65*128)
#define CP 40       // fp16 pitch for [128 x 32] k-chunk tiles
#define CTILE 10240 // 128*40*2 bytes
#define VP 136      // fp16 pitch for [32 x 128] B-trans chunk tiles
#define VTILE32 8704 // 32*136*2 bytes
#define OAP 72      // outproj pitch for k64 tiles
#define OATILE 9216  // 64*72*2
#define OBTILE 18432 // 128*72*2

typedef unsigned long long ull;
typedef unsigned int u32;

// ---------------- scratch (zero-initialized BSS; padding never written) ------
__device__ __half g_x0[Bb * SPAD * 128], g_x1[Bb * SPAD * 128];
__device__ __half g_wq0[Hh * Ee * Ee], g_wq1[Hh * Ee * Ee];
__device__ __half g_wk0[Hh * Ee * Ee], g_wk1[Hh * Ee * Ee];
__device__ __half g_wv0[Hh * Ee * Ee], g_wv1[Hh * Ee * Ee];
__device__ __half g_q0[72 * SPAD * 128], g_q1[72 * SPAD * 128];
__device__ __half g_k0[72 * SPAD * 128], g_k1[72 * SPAD * 128];
__device__ __half g_v0[72 * SPAD * 128], g_v1[72 * SPAD * 128];
__device__ __half g_p0[(size_t)72 * SPAD * SPAD], g_p1[(size_t)72 * SPAD * SPAD];
__device__ __half g_h0[ROWP * HE], g_h1[ROWP * HE];
__device__ __half g_w0[Ee * HE], g_w1[Ee * HE];

// ---------------- async copy / mma helpers ----------------
__device__ __forceinline__ u32 s2u(const void* p) {
    u32 a;
    asm("{ .reg .u64 t; cvta.to.shared.u64 t, %1; cvt.u32.u64 %0, t; }" : "=r"(a) : "l"(p));
    return a;
}
__device__ __forceinline__ void cp16(u32 smem, const void* g) {
    asm volatile("cp.async.cg.shared.global [%0], [%1], 16;" :: "r"(smem), "l"(g));
}
__device__ __forceinline__ void cp_commit() { asm volatile("cp.async.commit_group;" ::: "memory"); }
template <int N> __device__ __forceinline__ void cp_wait() {
    asm volatile("cp.async.wait_group %0;" :: "n"(N) : "memory");
}
__device__ __forceinline__ void ldmx4(u32& a0, u32& a1, u32& a2, u32& a3, u32 addr) {
    asm volatile("ldmatrix.sync.aligned.m8n8.x4.shared.b16 {%0,%1,%2,%3}, [%4];"
                 : "=r"(a0), "=r"(a1), "=r"(a2), "=r"(a3) : "r"(addr));
}
__device__ __forceinline__ void ldmx2(u32& b0, u32& b1, u32 addr) {
    asm volatile("ldmatrix.sync.aligned.m8n8.x2.shared.b16 {%0,%1}, [%2];"
                 : "=r"(b0), "=r"(b1) : "r"(addr));
}
__device__ __forceinline__ void ldmx2t(u32& b0, u32& b1, u32 addr) {
    asm volatile("ldmatrix.sync.aligned.m8n8.x2.trans.shared.b16 {%0,%1}, [%2];"
                 : "=r"(b0), "=r"(b1) : "r"(addr));
}
__device__ __forceinline__ void mma16816(float* c, u32 a0, u32 a1, u32 a2, u32 a3,
                                         u32 b0, u32 b1) {
    asm volatile("mma.sync.aligned.m16n8k16.row.col.f32.f16.f16.f32 "
                 "{%0,%1,%2,%3}, {%4,%5,%6,%7}, {%8,%9}, {%0,%1,%2,%3};"
                 : "+f"(c[0]), "+f"(c[1]), "+f"(c[2]), "+f"(c[3])
                 : "r"(a0), "r"(a1), "r"(a2), "r"(a3), "r"(b0), "r"(b1));
}
__device__ __forceinline__ void hsplit2(float x, __half& a, __half& b) {
    a = __float2half_rn(x);
    b = __float2half_rn(x - __half2float(a));
}

// =================================================================
// Kernel 0a: split W into fp16 levels
// =================================================================
__global__ __launch_bounds__(256) void wprep_kernel(const float* __restrict__ Wm)
{
    int idx = blockIdx.x * 256 + threadIdx.x;
    if (idx < Ee * HE) {
        __half a, b;
        hsplit2(Wm[idx], a, b);
        g_w0[idx] = a;
        g_w1[idx] = b;
    }
}

// =================================================================
// Kernel 0b: split Q/K/V weight matrices into fp16 levels (natural [h][e][f])
// =================================================================
__global__ __launch_bounds__(256) void qkvprep_kernel(
    const float* __restrict__ Qw, const float* __restrict__ Kw,
    const float* __restrict__ Vw)
{
    int idx = blockIdx.x * 256 + threadIdx.x;
    const int N = Hh * Ee * Ee;
    if (idx < 3 * N) {
        int z = idx / N, j = idx % N;
        const float* src = (z == 0) ? Qw : (z == 1) ? Kw : Vw;
        __half* d0 = (z == 0) ? g_wq0 : (z == 1) ? g_wk0 : g_wv0;
        __half* d1 = (z == 0) ? g_wq1 : (z == 1) ? g_wk1 : g_wv1;
        __half a, b;
        hsplit2(src[j], a, b);
        d0[j] = a;
        d1[j] = b;
    }
}

// =================================================================
// Kernel 0c: transpose x [B,E,S] -> xt splits [b][s][e] fp16 x2
// =================================================================
__global__ __launch_bounds__(256) void xprep_kernel(const float* __restrict__ x)
{
    __shared__ float ts[128 * 65];
    const int tid = threadIdx.x;
    const int s0 = blockIdx.x * 64;
    const int b = blockIdx.y;

    #pragma unroll
    for (int it = 0; it < 32; ++it) {
        int idx = tid + it * 256;
        int e = idx >> 6, sl = idx & 63;
        int s = s0 + sl;
        ts[e * 65 + sl] = (s < Ss) ? x[((size_t)b * Ee + e) * Ss + s] : 0.f;
    }
    __syncthreads();
    #pragma unroll
    for (int it = 0; it < 32; ++it) {
        int idx = tid + it * 256;
        int sl = idx >> 7, e = idx & 127;
        int s = s0 + sl;
        if (s < Ss) {
            __half a, bb;
            hsplit2(ts[e * 65 + sl], a, bb);
            size_t o = ((size_t)b * SPAD + s) * 128 + e;
            g_x0[o] = a;
            g_x1[o] = bb;
        }
    }
}

// =================================================================
// Kernel 1: projections via fp16 HMMA (3 products), 4 k32 chunks.
// Grid (9, 8, 27). 2 CTAs/SM.
// =================================================================
__global__ __launch_bounds__(256, 2) void proj_kernel()
{
    extern __shared__ __align__(16) unsigned char sm[];
    const u32 sbase = s2u(sm);
    const int tid = threadIdx.x, wid = tid >> 5, lane = tid & 31;
    const int m0 = blockIdx.x * 128;
    const int b = blockIdx.y;
    const int zt = blockIdx.z % 3, h = blockIdx.z / 3;
    const int wr = wid >> 2, wc = wid & 3;
    const int l15 = lane & 15;
    const int STG = 2 * CTILE + 2 * VTILE32;   // 37,888

    const __half* w0 = (zt == 0) ? g_wq0 : (zt == 1) ? g_wk0 : g_wv0;
    const __half* w1 = (zt == 0) ? g_wq1 : (zt == 1) ? g_wk1 : g_wv1;

    auto load_chunk = [&](int st, int ck) {
        const int e0 = ck * 32;
        for (int i = tid; i < 2048; i += 256) {
            if (i < 1024) {
                int t = i >> 9, rc = i & 511, r = rc >> 2, c = rc & 3;
                const __half* g = (t ? g_x1 : g_x0) +
                    ((size_t)b * SPAD + m0 + r) * 128 + e0 + c * 8;
                cp16(sbase + st * STG + t * CTILE + (r * CP + c * 8) * 2, g);
            } else {
                int j = i - 1024;
                int t = j >> 9, rc = j & 511, r = rc >> 4, c = rc & 15;
                const __half* g = (t ? w1 : w0) + ((size_t)h * 128 + e0 + r) * 128 + c * 8;
                cp16(sbase + st * STG + 2 * CTILE + t * VTILE32 + (r * VP + c * 8) * 2, g);
            }
        }
        cp_commit();
    };

    float acc[4][4][4];
    #pragma unroll
    for (int mt = 0; mt < 4; ++mt)
        #pragma unroll
        for (int nt = 0; nt < 4; ++nt)
            #pragma unroll
            for (int i = 0; i < 4; ++i) acc[mt][nt][i] = 0.f;

    load_chunk(0, 0);
    for (int ck = 0; ck < 4; ++ck) {
        if (ck + 1 < 4) load_chunk((ck + 1) & 1, ck + 1);
        if (ck + 1 < 4) cp_wait<1>(); else cp_wait<0>();
        __syncthreads();

        const u32 st = sbase + (ck & 1) * STG;
        const int PA[3] = {0, 0, 1};
        const int PB[3] = {0, 1, 0};
        #pragma unroll
        for (int l = 0; l < 3; ++l) {
            u32 abase = st + PA[l] * CTILE;
            u32 vbase = st + 2 * CTILE + PB[l] * VTILE32;
            #pragma unroll
            for (int k = 0; k < 2; ++k) {
                const int k0 = k * 16;
                u32 bfrag[4][2];
                u32 brow = vbase + ((k0 + l15) * VP) * 2;
                #pragma unroll
                for (int nt = 0; nt < 4; ++nt)
                    ldmx2t(bfrag[nt][0], bfrag[nt][1], brow + (wc * 32 + nt * 8) * 2);
                u32 arow = abase + ((wr * 64 + l15) * CP + k0 + ((lane >> 4) * 8)) * 2;
                #pragma unroll
                for (int mt = 0; mt < 4; ++mt) {
                    u32 a0, a1, a2, a3;
                    ldmx4(a0, a1, a2, a3, arow + (mt * 16 * CP) * 2);
                    #pragma unroll
                    for (int nt = 0; nt < 4; ++nt)
                        mma16816(acc[mt][nt], a0, a1, a2, a3, bfrag[nt][0], bfrag[nt][1]);
                }
            }
        }
        __syncthreads();
    }

    // epilogue: regs -> stage -> q/k/v fp16 splits
    float* stage = (float*)sm;   // [128][130]
    {
        int row = wr * 64 + (lane >> 2);
        int col = wc * 32 + (lane & 3) * 2;
        #pragma unroll
        for (int mt = 0; mt < 4; ++mt)
            #pragma unroll
            for (int nt = 0; nt < 4; ++nt) {
                float* c = acc[mt][nt];
                int rr = row + mt * 16, cc = col + nt * 8;
                *(float2*)&stage[rr * 130 + cc]       = make_float2(c[0], c[1]);
                *(float2*)&stage[(rr + 8) * 130 + cc] = make_float2(c[2], c[3]);
            }
    }
    __syncthreads();
    __half* d0 = (zt == 0) ? g_q0 : (zt == 1) ? g_k0 : g_v0;
    __half* d1 = (zt == 0) ? g_q1 : (zt == 1) ? g_k1 : g_v1;
    const int bh = b * Hh + h;
    for (int idx = tid; idx < 128 * 16; idx += 256) {
        int rr = idx >> 4, c8 = (idx & 15) * 8;
        int s = m0 + rr;
        if (s < Ss) {
            union { uint4 u; __half hh[8]; } h0, h1;
            #pragma unroll
            for (int c = 0; c < 8; ++c)
                hsplit2(stage[rr * 130 + c8 + c], h0.hh[c], h1.hh[c]);
            size_t base = ((size_t)bh * SPAD + s) * 128 + c8;
            *(uint4*)&d0[base] = h0.u;
            *(uint4*)&d1[base] = h1.u;
        }
    }
}

// =================================================================
// Kernel 2: scores. fp16 GEMM, 2-way split (3 products), 4 k32 chunks.
// Grid (81, 72). 2 CTAs/SM.
// =================================================================
__global__ __launch_bounds__(256, 2) void scores_kernel(float* __restrict__ atten)
{
    extern __shared__ __align__(16) unsigned char sm[];
    const u32 sbase = s2u(sm);
    const int tid = threadIdx.x, wid = tid >> 5, lane = tid & 31;
    const int m0 = (blockIdx.x / 9) * 128, n0r = (blockIdx.x % 9) * 128;
    const int bh = blockIdx.y;
    const int wr = wid >> 2, wc = wid & 3;
    const int l15 = lane & 15;
    const int STG = 4 * CTILE;

    auto load_chunk = [&](int st, int kc) {
        const int e0 = kc * 32;
        for (int i = tid; i < 2048; i += 256) {
            int t = i >> 9, rc = i & 511, r = rc >> 2, c = rc & 3;
            const __half* src = (t == 0) ? g_q0 : (t == 1) ? g_q1 : (t == 2) ? g_k0 : g_k1;
            int row0 = (t < 2) ? m0 : n0r;
            cp16(sbase + st * STG + t * CTILE + (r * CP + c * 8) * 2,
                 src + ((size_t)bh * SPAD + row0 + r) * 128 + e0 + c * 8);
        }
        cp_commit();
    };

    float acc[4][4][4];
    #pragma unroll
    for (int mt = 0; mt < 4; ++mt)
        #pragma unroll
        for (int nt = 0; nt < 4; ++nt)
            #pragma unroll
            for (int i = 0; i < 4; ++i) acc[mt][nt][i] = 0.f;

    load_chunk(0, 0);
    for (int kc = 0; kc < 4; ++kc) {
        if (kc + 1 < 4) load_chunk((kc + 1) & 1, kc + 1);
        if (kc + 1 < 4) cp_wait<1>(); else cp_wait<0>();
        __syncthreads();
        const u32 st = sbase + (kc & 1) * STG;
        const int PA[3] = {0, 0, 1};
        const int PB[3] = {0, 1, 0};
        #pragma unroll
        for (int l = 0; l < 3; ++l) {
            u32 abase = st + PA[l] * CTILE;
            u32 bbase = st + (2 + PB[l]) * CTILE;
            #pragma unroll
            for (int k = 0; k < 2; ++k) {
                const int k0 = k * 16;
                u32 bfrag[4][2];
                u32 brow = bbase + ((wc * 32 + (l15 & 7)) * CP + k0 + ((l15 >> 3) * 8)) * 2;
                #pragma unroll
                for (int nt = 0; nt < 4; ++nt)
                    ldmx2(bfrag[nt][0], bfrag[nt][1], brow + (nt * 8 * CP) * 2);
                u32 arow = abase + ((wr * 64 + l15) * CP + k0 + ((lane >> 4) * 8)) * 2;
                #pragma unroll
                for (int mt = 0; mt < 4; ++mt) {
                    u32 a0, a1, a2, a3;
                    ldmx4(a0, a1, a2, a3, arow + (mt * 16 * CP) * 2);
                    #pragma unroll
                    for (int nt = 0; nt < 4; ++nt)
                        mma16816(acc[mt][nt], a0, a1, a2, a3, bfrag[nt][0], bfrag[nt][1]);
                }
            }
        }
        __syncthreads();
    }

    float* stage = (float*)sm;   // [128][130]
    {
        int row = wr * 64 + (lane >> 2);
        int col = wc * 32 + (lane & 3) * 2;
        #pragma unroll
        for (int mt = 0; mt < 4; ++mt)
            #pragma unroll
            for (int nt = 0; nt < 4; ++nt) {
                float* c = acc[mt][nt];
                int rr = row + mt * 16, cc = col + nt * 8;
                *(float2*)&stage[rr * 130 + cc]       = make_float2(c[0], c[1]);
                *(float2*)&stage[(rr + 8) * 130 + cc] = make_float2(c[2], c[3]);
            }
    }
    __syncthreads();
    const float scl = 0.08838834764831845f;  // 1/sqrt(128)
    for (int idx = tid; idx < 128 * 128; idx += 256) {
        int rr = idx >> 7, c = idx & 127;
        int s = m0 + rr, t = n0r + c;
        if (s < Ss && t < Ss)
            atten[((size_t)bh * Ss + s) * Ss + t] = stage[rr * 130 + c] * scl;
    }
}

// =================================================================
// Kernel 3: softmax per row; writes fp32 atten AND fp16 2-way split of P.
// =================================================================
__global__ __launch_bounds__(128) void softmax_kernel(float* __restrict__ atten)
{
    __shared__ float buf[Ss];
    __shared__ float redm[4], reds[4];
    const int tid = threadIdx.x, wid = tid >> 5, lid = tid & 31;
    const int row = blockIdx.x;
    const int bh = row / Ss, s = row % Ss;
    float* p = atten + (size_t)row * Ss;

    float m = -3.0e38f;
    for (int c = tid; c < Ss; c += 128) { float v = p[c]; buf[c] = v; m = fmaxf(m, v); }
    #pragma unroll
    for (int o = 16; o; o >>= 1) m = fmaxf(m, __shfl_xor_sync(0xffffffffu, m, o));
    if (lid == 0) redm[wid] = m;
    __syncthreads();
    m = fmaxf(fmaxf(redm[0], redm[1]), fmaxf(redm[2], redm[3]));

    float sum = 0.f;
    for (int c = tid; c < Ss; c += 128) { float e = __expf(buf[c] - m); buf[c] = e; sum += e; }
    #pragma unroll
    for (int o = 16; o; o >>= 1) sum += __shfl_xor_sync(0xffffffffu, sum, o);
    if (lid == 0) reds[wid] = sum;
    __syncthreads();
    float inv = 1.f / (reds[0] + reds[1] + reds[2] + reds[3]);

    size_t pbase = ((size_t)bh * SPAD + s) * SPAD;
    for (int c = tid; c < Ss; c += 128) {
        float pr = buf[c] * inv;
        p[c] = pr;
        __half a, b;
        hsplit2(pr, a, b);
        g_p0[pbase + c] = a;
        g_p1[pbase + c] = b;
    }
}

// =================================================================
// Kernel 4: AV. fp16 2-way split (3 products), 36 k32 chunks.
// Grid (9, 72). 2 CTAs/SM.
// =================================================================
__global__ __launch_bounds__(256, 2) void av_kernel()
{
    extern __shared__ __align__(16) unsigned char sm[];
    const u32 sbase = s2u(sm);
    const int tid = threadIdx.x, wid = tid >> 5, lane = tid & 31;
    const int m0 = blockIdx.x * 128;
    const int bh = blockIdx.y;
    const int b = bh / Hh, h = bh % Hh;
    const int wr = wid >> 2, wc = wid & 3;
    const int l15 = lane & 15;
    const int STG = 2 * CTILE + 2 * VTILE32;   // 37,888

    auto load_chunk = [&](int st, int ck) {
        const int t0 = ck * 32;
        for (int i = tid; i < 2048; i += 256) {
            if (i < 1024) {
                int t = i >> 9, rc = i & 511, r = rc >> 2, c = rc & 3;
                const __half* g = (t ? g_p1 : g_p0) +
                    ((size_t)bh * SPAD + m0 + r) * SPAD + t0 + c * 8;
                cp16(sbase + st * STG + t * CTILE + (r * CP + c * 8) * 2, g);
            } else {
                int j = i - 1024;
                int t = j >> 9, rc = j & 511, r = rc >> 4, c = rc & 15;
                const __half* g = (t ? g_v1 : g_v0) +
                    ((size_t)bh * SPAD + t0 + r) * 128 + c * 8;
                cp16(sbase + st * STG + 2 * CTILE + t * VTILE32 + (r * VP + c * 8) * 2, g);
            }
        }
        cp_commit();
    };

    float acc[4][4][4];
    #pragma unroll
    for (int mt = 0; mt < 4; ++mt)
        #pragma unroll
        for (int nt = 0; nt < 4; ++nt)
            #pragma unroll
            for (int i = 0; i < 4; ++i) acc[mt][nt][i] = 0.f;

    load_chunk(0, 0);
    for (int ck = 0; ck < 36; ++ck) {
        if (ck + 1 < 36) load_chunk((ck + 1) & 1, ck + 1);
        if (ck + 1 < 36) cp_wait<1>(); else cp_wait<0>();
        __syncthreads();

        const u32 st = sbase + (ck & 1) * STG;
        const int PA[3] = {0, 0, 1};
        const int PB[3] = {0, 1, 0};
        #pragma unroll
        for (int l = 0; l < 3; ++l) {
            u32 abase = st + PA[l] * CTILE;
            u32 vbase = st + 2 * CTILE + PB[l] * VTILE32;
            #pragma unroll
            for (int k = 0; k < 2; ++k) {
                const int k0 = k * 16;
                u32 bfrag[4][2];
                u32 brow = vbase + ((k0 + l15) * VP) * 2;
                #pragma unroll
                for (int nt = 0; nt < 4; ++nt)
                    ldmx2t(bfrag[nt][0], bfrag[nt][1], brow + (wc * 32 + nt * 8) * 2);
                u32 arow = abase + ((wr * 64 + l15) * CP + k0 + ((lane >> 4) * 8)) * 2;
                #pragma unroll
                for (int mt = 0; mt < 4; ++mt) {
                    u32 a0, a1, a2, a3;
                    ldmx4(a0, a1, a2, a3, arow + (mt * 16 * CP) * 2);
                    #pragma unroll
                    for (int nt = 0; nt < 4; ++nt)
                        mma16816(acc[mt][nt], a0, a1, a2, a3, bfrag[nt][0], bfrag[nt][1]);
                }
            }
        }
        __syncthreads();
    }

    float* stage = (float*)sm;   // [128][130]
    {
        int row = wr * 64 + (lane >> 2);
        int col = wc * 32 + (lane & 3) * 2;
        #pragma unroll
        for (int mt = 0; mt < 4; ++mt)
            #pragma unroll
            for (int nt = 0; nt < 4; ++nt) {
                float* c = acc[mt][nt];
                int rr = row + mt * 16, cc = col + nt * 8;
                *(float2*)&stage[rr * 130 + cc]       = make_float2(c[0], c[1]);
                *(float2*)&stage[(rr + 8) * 130 + cc] = make_float2(c[2], c[3]);
            }
    }
    __syncthreads();
    for (int idx = tid; idx < 128 * 16; idx += 256) {
        int rr = idx >> 4, c8 = (idx & 15) * 8;
        int s = m0 + rr;
        if (s < Ss) {
            union { uint4 u; __half hh[8]; } h0, h1;
            #pragma unroll
            for (int c = 0; c < 8; ++c)
                hsplit2(stage[rr * 130 + c8 + c], h0.hh[c], h1.hh[c]);
            size_t base = ((size_t)b * Ss + s) * HE + h * Ee + c8;
            *(uint4*)&g_h0[base] = h0.u;
            *(uint4*)&g_h1[base] = h1.u;
        }
    }
}

// =================================================================
// Kernel 5: outproj via fp16 HMMA (3 products), 18 k64 chunks. 2 CTAs/SM.
// =================================================================
__global__ __launch_bounds__(256, 2) void outproj_kernel(
    const float* __restrict__ bias, float* __restrict__ out)
{
    extern __shared__ __align__(16) unsigned char sm[];
    const u32 sbase = s2u(sm);
    const int tid = threadIdx.x, wid = tid >> 5, lane = tid & 31;
    const int row0 = blockIdx.x * 64;
    const int wr = wid >> 2, wc = wid & 3;
    const int l15 = lane & 15;
    const int STG = 2 * OATILE + 2 * OBTILE;   // 55,296

    auto load_chunk = [&](int st, int ck) {
        const int k0g = ck * 64;
        for (int i = tid; i < 3072; i += 256) {
            if (i < 1024) {
                int t = i >> 9, rc = i & 511, r = rc >> 3, c = rc & 7;
                const __half* g = (t ? g_h1 : g_h0) + (size_t)(row0 + r) * HE + k0g + c * 8;
                cp16(sbase + st * STG + t * OATILE + (r * OAP + c * 8) * 2, g);
            } else {
                int j = i - 1024;
                int t = j >> 10, rc = j & 1023, r = rc >> 3, c = rc & 7;
                const __half* g = (t ? g_w1 : g_w0) + (size_t)r * HE + k0g + c * 8;
                cp16(sbase + st * STG + 2 * OATILE + t * OBTILE + (r * OAP + c * 8) * 2, g);
            }
        }
        cp_commit();
    };

    float acc[2][4][4];
    #pragma unroll
    for (int mt = 0; mt < 2; ++mt)
        #pragma unroll
        for (int nt = 0; nt < 4; ++nt)
            #pragma unroll
            for (int i = 0; i < 4; ++i) acc[mt][nt][i] = 0.f;

    load_chunk(0, 0);
    for (int ck = 0; ck < 18; ++ck) {
        if (ck + 1 < 18) load_chunk((ck + 1) & 1, ck + 1);
        if (ck + 1 < 18) cp_wait<1>(); else cp_wait<0>();
        __syncthreads();

        const u32 st = sbase + (ck & 1) * STG;
        const int PA[3] = {0, 0, 1};
        const int PB[3] = {0, 1, 0};
        #pragma unroll
        for (int l = 0; l < 3; ++l) {
            u32 abase = st + PA[l] * OATILE;
            u32 bbase = st + 2 * OATILE + PB[l] * OBTILE;
            #pragma unroll
            for (int k = 0; k < 4; ++k) {
                const int k0 = k * 16;
                u32 bfrag[4][2];
                u32 brow = bbase + ((wc * 32 + (l15 & 7)) * OAP + k0 + ((l15 >> 3) * 8)) * 2;
                #pragma unroll
                for (int nt = 0; nt < 4; ++nt)
                    ldmx2(bfrag[nt][0], bfrag[nt][1], brow + (nt * 8 * OAP) * 2);
                u32 arow = abase + ((wr * 32 + l15) * OAP + k0 + ((lane >> 4) * 8)) * 2;
                #pragma unroll
                for (int mt = 0; mt < 2; ++mt) {
                    u32 a0, a1, a2, a3;
                    ldmx4(a0, a1, a2, a3, arow + (mt * 16 * OAP) * 2);
                    #pragma unroll
                    for (int nt = 0; nt < 4; ++nt)
                        mma16816(acc[mt][nt], a0, a1, a2, a3, bfrag[nt][0], bfrag[nt][1]);
                }
            }
        }
        __syncthreads();
    }

    float* stage = (float*)sm;
    {
        int row = wr * 32 + (lane >> 2);
        int col = wc * 32 + (lane & 3) * 2;
        #pragma unroll
        for (int mt = 0; mt < 2; ++mt)
            #pragma unroll
            for (int nt = 0; nt < 4; ++nt) {
                float* c = acc[mt][nt];
                int rr = row + mt * 16, cc = col + nt * 8;
                stage[rr * 129 + cc]           = c[0];
                stage[rr * 129 + cc + 1]       = c[1];
                stage[(rr + 8) * 129 + cc]     = c[2];
                stage[(rr + 8) * 129 + cc + 1] = c[3];
            }
    }
    __syncthreads();
    for (int idx = tid; idx < 128 * 64; idx += 256) {
        int e = idx >> 6, rr = idx & 63;
        int rg = row0 + rr;
        if (rg < Bb * Ss) {
            int b = rg / Ss, s = rg % Ss;
            out[((size_t)b * Ee + e) * Ss + s] = stage[rr * 129 + e] + bias[e];
        }
    }
}

// =================================================================
extern "C" void kernel_launch(void* const* d_in, const int* in_sizes, int n_in,
                              void* d_out, int out_size)
{
    const float* x    = (const float*)d_in[0];
    const float* Qw   = (const float*)d_in[1];
    const float* Kw   = (const float*)d_in[2];
    const float* Vw   = (const float*)d_in[3];
    const float* Wm   = (const float*)d_in[4];
    const float* bias = (const float*)d_in[5];

    float* out   = (float*)d_out;                    // [B,E,S]
    float* atten = out + (size_t)Bb * Ee * Ss;       // [B,H,S,S]

    const int smemP = 2 * (2 * CTILE + 2 * VTILE32); // 75,776
    const int smemS = 2 * 4 * CTILE;                 // 81,920
    const int smemA = 2 * (2 * CTILE + 2 * VTILE32); // 75,776
    const int smemO = 2 * (2 * OATILE + 2 * OBTILE); // 110,592

    cudaFuncSetAttribute(proj_kernel,    cudaFuncAttributeMaxDynamicSharedMemorySize, smemP);
    cudaFuncSetAttribute(scores_kernel,  cudaFuncAttributeMaxDynamicSharedMemorySize, smemS);
    cudaFuncSetAttribute(av_kernel,      cudaFuncAttributeMaxDynamicSharedMemorySize, smemA);
    cudaFuncSetAttribute(outproj_kernel, cudaFuncAttributeMaxDynamicSharedMemorySize, smemO);

    wprep_kernel<<<576, 256>>>(Wm);
    qkvprep_kernel<<<1728, 256>>>(Qw, Kw, Vw);
    xprep_kernel<<<dim3(17, Bb), 256>>>(x);
    proj_kernel<<<dim3(9, Bb, 27), 256, smemP>>>();
    scores_kernel<<<dim3(81, Bb * Hh), 256, smemS>>>(atten);
    softmax_kernel<<<Bb * Hh * Ss, 128>>>(atten);
    av_kernel<<<dim3(9, Bb * Hh), 256, smemA>>>();
    outproj_kernel<<<130, 256, smemO>>>(bias, out);
}

// round 10
// speedup vs baseline: 2.8944x; 1.0941x over previous
#include <cuda_runtime.h>
#include <cuda_fp16.h>

#define Bb 8
#define Hh 9
#define Ee 128
#define Ss 1025
#define SPAD 1152   // padded sequence (rows/cols >=1025 stay zero-initialized)
#define HE 1152
#define ROWP 8320   // padded out-proj row count (65*128)
#define CP 40       // fp16 pitch for [128 x 32] k-chunk tiles
#define CTILE 10240 // 128*40*2 bytes
#define VP 136      // fp16 pitch for [32 x 128] B-trans chunk tiles
#define VTILE32 8704 // 32*136*2 bytes
#define OAP 72      // outproj pitch for k64 tiles
#define OATILE 9216  // 64*72*2
#define OBTILE 18432 // 128*72*2

typedef unsigned long long ull;
typedef unsigned int u32;

// ---------------- scratch (zero-initialized BSS; padding never written) ------
__device__ __half g_x0[Bb * SPAD * 128], g_x1[Bb * SPAD * 128];
__device__ __half g_wq0[Hh * Ee * Ee], g_wq1[Hh * Ee * Ee];
__device__ __half g_wk0[Hh * Ee * Ee], g_wk1[Hh * Ee * Ee];
__device__ __half g_wv0[Hh * Ee * Ee], g_wv1[Hh * Ee * Ee];
__device__ __half g_q0[72 * SPAD * 128], g_q1[72 * SPAD * 128];
__device__ __half g_k0[72 * SPAD * 128], g_k1[72 * SPAD * 128];
__device__ __half g_v0[72 * SPAD * 128], g_v1[72 * SPAD * 128];
__device__ __half g_p0[(size_t)72 * SPAD * SPAD];
__device__ __half g_h0[ROWP * HE], g_h1[ROWP * HE];
__device__ __half g_w0[Ee * HE], g_w1[Ee * HE];

// ---------------- async copy / mma helpers ----------------
__device__ __forceinline__ u32 s2u(const void* p) {
    u32 a;
    asm("{ .reg .u64 t; cvta.to.shared.u64 t, %1; cvt.u32.u64 %0, t; }" : "=r"(a) : "l"(p));
    return a;
}
__device__ __forceinline__ void cp16(u32 smem, const void* g) {
    asm volatile("cp.async.cg.shared.global [%0], [%1], 16;" :: "r"(smem), "l"(g));
}
__device__ __forceinline__ void cp_commit() { asm volatile("cp.async.commit_group;" ::: "memory"); }
template <int N> __device__ __forceinline__ void cp_wait() {
    asm volatile("cp.async.wait_group %0;" :: "n"(N) : "memory");
}
__device__ __forceinline__ void ldmx4(u32& a0, u32& a1, u32& a2, u32& a3, u32 addr) {
    asm volatile("ldmatrix.sync.aligned.m8n8.x4.shared.b16 {%0,%1,%2,%3}, [%4];"
                 : "=r"(a0), "=r"(a1), "=r"(a2), "=r"(a3) : "r"(addr));
}
__device__ __forceinline__ void ldmx2(u32& b0, u32& b1, u32 addr) {
    asm volatile("ldmatrix.sync.aligned.m8n8.x2.shared.b16 {%0,%1}, [%2];"
                 : "=r"(b0), "=r"(b1) : "r"(addr));
}
__device__ __forceinline__ void ldmx2t(u32& b0, u32& b1, u32 addr) {
    asm volatile("ldmatrix.sync.aligned.m8n8.x2.trans.shared.b16 {%0,%1}, [%2];"
                 : "=r"(b0), "=r"(b1) : "r"(addr));
}
__device__ __forceinline__ void mma16816(float* c, u32 a0, u32 a1, u32 a2, u32 a3,
                                         u32 b0, u32 b1) {
    asm volatile("mma.sync.aligned.m16n8k16.row.col.f32.f16.f16.f32 "
                 "{%0,%1,%2,%3}, {%4,%5,%6,%7}, {%8,%9}, {%0,%1,%2,%3};"
                 : "+f"(c[0]), "+f"(c[1]), "+f"(c[2]), "+f"(c[3])
                 : "r"(a0), "r"(a1), "r"(a2), "r"(a3), "r"(b0), "r"(b1));
}
__device__ __forceinline__ void hsplit2(float x, __half& a, __half& b) {
    a = __float2half_rn(x);
    b = __float2half_rn(x - __half2float(a));
}

// =================================================================
// Kernel 0a: split W into fp16 levels
// =================================================================
__global__ __launch_bounds__(256) void wprep_kernel(const float* __restrict__ Wm)
{
    int idx = blockIdx.x * 256 + threadIdx.x;
    if (idx < Ee * HE) {
        __half a, b;
        hsplit2(Wm[idx], a, b);
        g_w0[idx] = a;
        g_w1[idx] = b;
    }
}

// =================================================================
// Kernel 0b: split Q/K/V weight matrices into fp16 levels (natural [h][e][f])
// =================================================================
__global__ __launch_bounds__(256) void qkvprep_kernel(
    const float* __restrict__ Qw, const float* __restrict__ Kw,
    const float* __restrict__ Vw)
{
    int idx = blockIdx.x * 256 + threadIdx.x;
    const int N = Hh * Ee * Ee;
    if (idx < 3 * N) {
        int z = idx / N, j = idx % N;
        const float* src = (z == 0) ? Qw : (z == 1) ? Kw : Vw;
        __half* d0 = (z == 0) ? g_wq0 : (z == 1) ? g_wk0 : g_wv0;
        __half* d1 = (z == 0) ? g_wq1 : (z == 1) ? g_wk1 : g_wv1;
        __half a, b;
        hsplit2(src[j], a, b);
        d0[j] = a;
        d1[j] = b;
    }
}

// =================================================================
// Kernel 0c: transpose x [B,E,S] -> xt splits [b][s][e] fp16 x2
// =================================================================
__global__ __launch_bounds__(256) void xprep_kernel(const float* __restrict__ x)
{
    __shared__ float ts[128 * 65];
    const int tid = threadIdx.x;
    const int s0 = blockIdx.x * 64;
    const int b = blockIdx.y;

    #pragma unroll
    for (int it = 0; it < 32; ++it) {
        int idx = tid + it * 256;
        int e = idx >> 6, sl = idx & 63;
        int s = s0 + sl;
        ts[e * 65 + sl] = (s < Ss) ? x[((size_t)b * Ee + e) * Ss + s] : 0.f;
    }
    __syncthreads();
    #pragma unroll
    for (int it = 0; it < 32; ++it) {
        int idx = tid + it * 256;
        int sl = idx >> 7, e = idx & 127;
        int s = s0 + sl;
        if (s < Ss) {
            __half a, bb;
            hsplit2(ts[e * 65 + sl], a, bb);
            size_t o = ((size_t)b * SPAD + s) * 128 + e;
            g_x0[o] = a;
            g_x1[o] = bb;
        }
    }
}

// =================================================================
// Kernel 1: projections via fp16 HMMA (3 products), 4 k32 chunks.
// Grid (9, 8, 27). 2 CTAs/SM.
// =================================================================
__global__ __launch_bounds__(256, 2) void proj_kernel()
{
    extern __shared__ __align__(16) unsigned char sm[];
    const u32 sbase = s2u(sm);
    const int tid = threadIdx.x, wid = tid >> 5, lane = tid & 31;
    const int m0 = blockIdx.x * 128;
    const int b = blockIdx.y;
    const int zt = blockIdx.z % 3, h = blockIdx.z / 3;
    const int wr = wid >> 2, wc = wid & 3;
    const int l15 = lane & 15;
    const int STG = 2 * CTILE + 2 * VTILE32;   // 37,888

    const __half* w0 = (zt == 0) ? g_wq0 : (zt == 1) ? g_wk0 : g_wv0;
    const __half* w1 = (zt == 0) ? g_wq1 : (zt == 1) ? g_wk1 : g_wv1;

    auto load_chunk = [&](int st, int ck) {
        const int e0 = ck * 32;
        for (int i = tid; i < 2048; i += 256) {
            if (i < 1024) {
                int t = i >> 9, rc = i & 511, r = rc >> 2, c = rc & 3;
                const __half* g = (t ? g_x1 : g_x0) +
                    ((size_t)b * SPAD + m0 + r) * 128 + e0 + c * 8;
                cp16(sbase + st * STG + t * CTILE + (r * CP + c * 8) * 2, g);
            } else {
                int j = i - 1024;
                int t = j >> 9, rc = j & 511, r = rc >> 4, c = rc & 15;
                const __half* g = (t ? w1 : w0) + ((size_t)h * 128 + e0 + r) * 128 + c * 8;
                cp16(sbase + st * STG + 2 * CTILE + t * VTILE32 + (r * VP + c * 8) * 2, g);
            }
        }
        cp_commit();
    };

    float acc[4][4][4];
    #pragma unroll
    for (int mt = 0; mt < 4; ++mt)
        #pragma unroll
        for (int nt = 0; nt < 4; ++nt)
            #pragma unroll
            for (int i = 0; i < 4; ++i) acc[mt][nt][i] = 0.f;

    load_chunk(0, 0);
    for (int ck = 0; ck < 4; ++ck) {
        if (ck + 1 < 4) load_chunk((ck + 1) & 1, ck + 1);
        if (ck + 1 < 4) cp_wait<1>(); else cp_wait<0>();
        __syncthreads();

        const u32 st = sbase + (ck & 1) * STG;
        const int PA[3] = {0, 0, 1};
        const int PB[3] = {0, 1, 0};
        #pragma unroll
        for (int l = 0; l < 3; ++l) {
            u32 abase = st + PA[l] * CTILE;
            u32 vbase = st + 2 * CTILE + PB[l] * VTILE32;
            #pragma unroll
            for (int k = 0; k < 2; ++k) {
                const int k0 = k * 16;
                u32 bfrag[4][2];
                u32 brow = vbase + ((k0 + l15) * VP) * 2;
                #pragma unroll
                for (int nt = 0; nt < 4; ++nt)
                    ldmx2t(bfrag[nt][0], bfrag[nt][1], brow + (wc * 32 + nt * 8) * 2);
                u32 arow = abase + ((wr * 64 + l15) * CP + k0 + ((lane >> 4) * 8)) * 2;
                #pragma unroll
                for (int mt = 0; mt < 4; ++mt) {
                    u32 a0, a1, a2, a3;
                    ldmx4(a0, a1, a2, a3, arow + (mt * 16 * CP) * 2);
                    #pragma unroll
                    for (int nt = 0; nt < 4; ++nt)
                        mma16816(acc[mt][nt], a0, a1, a2, a3, bfrag[nt][0], bfrag[nt][1]);
                }
            }
        }
        __syncthreads();
    }

    // epilogue: regs -> stage -> q/k/v fp16 splits
    float* stage = (float*)sm;   // [128][130]
    {
        int row = wr * 64 + (lane >> 2);
        int col = wc * 32 + (lane & 3) * 2;
        #pragma unroll
        for (int mt = 0; mt < 4; ++mt)
            #pragma unroll
            for (int nt = 0; nt < 4; ++nt) {
                float* c = acc[mt][nt];
                int rr = row + mt * 16, cc = col + nt * 8;
                *(float2*)&stage[rr * 130 + cc]       = make_float2(c[0], c[1]);
                *(float2*)&stage[(rr + 8) * 130 + cc] = make_float2(c[2], c[3]);
            }
    }
    __syncthreads();
    __half* d0 = (zt == 0) ? g_q0 : (zt == 1) ? g_k0 : g_v0;
    __half* d1 = (zt == 0) ? g_q1 : (zt == 1) ? g_k1 : g_v1;
    const int bh = b * Hh + h;
    for (int idx = tid; idx < 128 * 16; idx += 256) {
        int rr = idx >> 4, c8 = (idx & 15) * 8;
        int s = m0 + rr;
        if (s < Ss) {
            union { uint4 u; __half hh[8]; } h0, h1;
            #pragma unroll
            for (int c = 0; c < 8; ++c)
                hsplit2(stage[rr * 130 + c8 + c], h0.hh[c], h1.hh[c]);
            size_t base = ((size_t)bh * SPAD + s) * 128 + c8;
            *(uint4*)&d0[base] = h0.u;
            *(uint4*)&d1[base] = h1.u;
        }
    }
}

// =================================================================
// Kernel 2: scores. fp16 GEMM, 2-way split (3 products), 4 k32 chunks.
// Grid (81, 72). 2 CTAs/SM.
// =================================================================
__global__ __launch_bounds__(256, 2) void scores_kernel(float* __restrict__ atten)
{
    extern __shared__ __align__(16) unsigned char sm[];
    const u32 sbase = s2u(sm);
    const int tid = threadIdx.x, wid = tid >> 5, lane = tid & 31;
    const int m0 = (blockIdx.x / 9) * 128, n0r = (blockIdx.x % 9) * 128;
    const int bh = blockIdx.y;
    const int wr = wid >> 2, wc = wid & 3;
    const int l15 = lane & 15;
    const int STG = 4 * CTILE;

    auto load_chunk = [&](int st, int kc) {
        const int e0 = kc * 32;
        for (int i = tid; i < 2048; i += 256) {
            int t = i >> 9, rc = i & 511, r = rc >> 2, c = rc & 3;
            const __half* src = (t == 0) ? g_q0 : (t == 1) ? g_q1 : (t == 2) ? g_k0 : g_k1;
            int row0 = (t < 2) ? m0 : n0r;
            cp16(sbase + st * STG + t * CTILE + (r * CP + c * 8) * 2,
                 src + ((size_t)bh * SPAD + row0 + r) * 128 + e0 + c * 8);
        }
        cp_commit();
    };

    float acc[4][4][4];
    #pragma unroll
    for (int mt = 0; mt < 4; ++mt)
        #pragma unroll
        for (int nt = 0; nt < 4; ++nt)
            #pragma unroll
            for (int i = 0; i < 4; ++i) acc[mt][nt][i] = 0.f;

    load_chunk(0, 0);
    for (int kc = 0; kc < 4; ++kc) {
        if (kc + 1 < 4) load_chunk((kc + 1) & 1, kc + 1);
        if (kc + 1 < 4) cp_wait<1>(); else cp_wait<0>();
        __syncthreads();
        const u32 st = sbase + (kc & 1) * STG;
        const int PA[3] = {0, 0, 1};
        const int PB[3] = {0, 1, 0};
        #pragma unroll
        for (int l = 0; l < 3; ++l) {
            u32 abase = st + PA[l] * CTILE;
            u32 bbase = st + (2 + PB[l]) * CTILE;
            #pragma unroll
            for (int k = 0; k < 2; ++k) {
                const int k0 = k * 16;
                u32 bfrag[4][2];
                u32 brow = bbase + ((wc * 32 + (l15 & 7)) * CP + k0 + ((l15 >> 3) * 8)) * 2;
                #pragma unroll
                for (int nt = 0; nt < 4; ++nt)
                    ldmx2(bfrag[nt][0], bfrag[nt][1], brow + (nt * 8 * CP) * 2);
                u32 arow = abase + ((wr * 64 + l15) * CP + k0 + ((lane >> 4) * 8)) * 2;
                #pragma unroll
                for (int mt = 0; mt < 4; ++mt) {
                    u32 a0, a1, a2, a3;
                    ldmx4(a0, a1, a2, a3, arow + (mt * 16 * CP) * 2);
                    #pragma unroll
                    for (int nt = 0; nt < 4; ++nt)
                        mma16816(acc[mt][nt], a0, a1, a2, a3, bfrag[nt][0], bfrag[nt][1]);
                }
            }
        }
        __syncthreads();
    }

    float* stage = (float*)sm;   // [128][130]
    {
        int row = wr * 64 + (lane >> 2);
        int col = wc * 32 + (lane & 3) * 2;
        #pragma unroll
        for (int mt = 0; mt < 4; ++mt)
            #pragma unroll
            for (int nt = 0; nt < 4; ++nt) {
                float* c = acc[mt][nt];
                int rr = row + mt * 16, cc = col + nt * 8;
                *(float2*)&stage[rr * 130 + cc]       = make_float2(c[0], c[1]);
                *(float2*)&stage[(rr + 8) * 130 + cc] = make_float2(c[2], c[3]);
            }
    }
    __syncthreads();
    const float scl = 0.08838834764831845f;  // 1/sqrt(128)
    for (int idx = tid; idx < 128 * 128; idx += 256) {
        int rr = idx >> 7, c = idx & 127;
        int s = m0 + rr, t = n0r + c;
        if (s < Ss && t < Ss)
            atten[((size_t)bh * Ss + s) * Ss + t] = stage[rr * 130 + c] * scl;
    }
}

// =================================================================
// Kernel 3: softmax per row; writes fp32 atten AND single fp16 P0.
// =================================================================
__global__ __launch_bounds__(128) void softmax_kernel(float* __restrict__ atten)
{
    __shared__ float buf[Ss];
    __shared__ float redm[4], reds[4];
    const int tid = threadIdx.x, wid = tid >> 5, lid = tid & 31;
    const int row = blockIdx.x;
    const int bh = row / Ss, s = row % Ss;
    float* p = atten + (size_t)row * Ss;

    float m = -3.0e38f;
    for (int c = tid; c < Ss; c += 128) { float v = p[c]; buf[c] = v; m = fmaxf(m, v); }
    #pragma unroll
    for (int o = 16; o; o >>= 1) m = fmaxf(m, __shfl_xor_sync(0xffffffffu, m, o));
    if (lid == 0) redm[wid] = m;
    __syncthreads();
    m = fmaxf(fmaxf(redm[0], redm[1]), fmaxf(redm[2], redm[3]));

    float sum = 0.f;
    for (int c = tid; c < Ss; c += 128) { float e = __expf(buf[c] - m); buf[c] = e; sum += e; }
    #pragma unroll
    for (int o = 16; o; o >>= 1) sum += __shfl_xor_sync(0xffffffffu, sum, o);
    if (lid == 0) reds[wid] = sum;
    __syncthreads();
    float inv = 1.f / (reds[0] + reds[1] + reds[2] + reds[3]);

    __half* prow = g_p0 + ((size_t)bh * SPAD + s) * SPAD;
    for (int c2 = tid; c2 * 2 < Ss; c2 += 128) {
        int c = c2 * 2;
        float pr0 = buf[c] * inv;
        p[c] = pr0;
        if (c + 1 < Ss) {
            float pr1 = buf[c + 1] * inv;
            p[c + 1] = pr1;
            *(__half2*)&prow[c] = __floats2half2_rn(pr0, pr1);
        } else {
            prow[c] = __float2half_rn(pr0);
        }
    }
}

// =================================================================
// Kernel 4: AV. fp16 P0 x V split2 (2 products), 36 k32 chunks.
// Grid (9, 72). 2 CTAs/SM. Emits ho fp16 split2.
// smem = max(2*STG, 128*130*4) = 66,560 B (stage buffer is the max)
// =================================================================
__global__ __launch_bounds__(256, 2) void av_kernel()
{
    extern __shared__ __align__(16) unsigned char sm[];
    const u32 sbase = s2u(sm);
    const int tid = threadIdx.x, wid = tid >> 5, lane = tid & 31;
    const int m0 = blockIdx.x * 128;
    const int bh = blockIdx.y;
    const int b = bh / Hh, h = bh % Hh;
    const int wr = wid >> 2, wc = wid & 3;
    const int l15 = lane & 15;
    const int STG = CTILE + 2 * VTILE32;   // 27,648

    auto load_chunk = [&](int st, int ck) {
        const int t0 = ck * 32;
        for (int i = tid; i < 1536; i += 256) {
            if (i < 512) {
                int r = i >> 2, c = i & 3;
                const __half* g = g_p0 + ((size_t)bh * SPAD + m0 + r) * SPAD + t0 + c * 8;
                cp16(sbase + st * STG + (r * CP + c * 8) * 2, g);
            } else {
                int j = i - 512;
                int t = j >> 9, rc = j & 511, r = rc >> 4, c = rc & 15;
                const __half* g = (t ? g_v1 : g_v0) +
                    ((size_t)bh * SPAD + t0 + r) * 128 + c * 8;
                cp16(sbase + st * STG + CTILE + t * VTILE32 + (r * VP + c * 8) * 2, g);
            }
        }
        cp_commit();
    };

    float acc[4][4][4];
    #pragma unroll
    for (int mt = 0; mt < 4; ++mt)
        #pragma unroll
        for (int nt = 0; nt < 4; ++nt)
            #pragma unroll
            for (int i = 0; i < 4; ++i) acc[mt][nt][i] = 0.f;

    load_chunk(0, 0);
    for (int ck = 0; ck < 36; ++ck) {
        if (ck + 1 < 36) load_chunk((ck + 1) & 1, ck + 1);
        if (ck + 1 < 36) cp_wait<1>(); else cp_wait<0>();
        __syncthreads();

        const u32 st = sbase + (ck & 1) * STG;
        #pragma unroll
        for (int l = 0; l < 2; ++l) {
            u32 abase = st;
            u32 vbase = st + CTILE + l * VTILE32;
            #pragma unroll
            for (int k = 0; k < 2; ++k) {
                const int k0 = k * 16;
                u32 bfrag[4][2];
                u32 brow = vbase + ((k0 + l15) * VP) * 2;
                #pragma unroll
                for (int nt = 0; nt < 4; ++nt)
                    ldmx2t(bfrag[nt][0], bfrag[nt][1], brow + (wc * 32 + nt * 8) * 2);
                u32 arow = abase + ((wr * 64 + l15) * CP + k0 + ((lane >> 4) * 8)) * 2;
                #pragma unroll
                for (int mt = 0; mt < 4; ++mt) {
                    u32 a0, a1, a2, a3;
                    ldmx4(a0, a1, a2, a3, arow + (mt * 16 * CP) * 2);
                    #pragma unroll
                    for (int nt = 0; nt < 4; ++nt)
                        mma16816(acc[mt][nt], a0, a1, a2, a3, bfrag[nt][0], bfrag[nt][1]);
                }
            }
        }
        __syncthreads();
    }

    float* stage = (float*)sm;   // [128][130] = 66,560 B (fits smemA)
    {
        int row = wr * 64 + (lane >> 2);
        int col = wc * 32 + (lane & 3) * 2;
        #pragma unroll
        for (int mt = 0; mt < 4; ++mt)
            #pragma unroll
            for (int nt = 0; nt < 4; ++nt) {
                float* c = acc[mt][nt];
                int rr = row + mt * 16, cc = col + nt * 8;
                *(float2*)&stage[rr * 130 + cc]       = make_float2(c[0], c[1]);
                *(float2*)&stage[(rr + 8) * 130 + cc] = make_float2(c[2], c[3]);
            }
    }
    __syncthreads();
    for (int idx = tid; idx < 128 * 16; idx += 256) {
        int rr = idx >> 4, c8 = (idx & 15) * 8;
        int s = m0 + rr;
        if (s < Ss) {
            union { uint4 u; __half hh[8]; } h0, h1;
            #pragma unroll
            for (int c = 0; c < 8; ++c)
                hsplit2(stage[rr * 130 + c8 + c], h0.hh[c], h1.hh[c]);
            size_t base = ((size_t)b * Ss + s) * HE + h * Ee + c8;
            *(uint4*)&g_h0[base] = h0.u;
            *(uint4*)&g_h1[base] = h1.u;
        }
    }
}

// =================================================================
// Kernel 5: outproj via fp16 HMMA (3 products), 18 k64 chunks. 2 CTAs/SM.
// =================================================================
__global__ __launch_bounds__(256, 2) void outproj_kernel(
    const float* __restrict__ bias, float* __restrict__ out)
{
    extern __shared__ __align__(16) unsigned char sm[];
    const u32 sbase = s2u(sm);
    const int tid = threadIdx.x, wid = tid >> 5, lane = tid & 31;
    const int row0 = blockIdx.x * 64;
    const int wr = wid >> 2, wc = wid & 3;
    const int l15 = lane & 15;
    const int STG = 2 * OATILE + 2 * OBTILE;   // 55,296

    auto load_chunk = [&](int st, int ck) {
        const int k0g = ck * 64;
        for (int i = tid; i < 3072; i += 256) {
            if (i < 1024) {
                int t = i >> 9, rc = i & 511, r = rc >> 3, c = rc & 7;
                const __half* g = (t ? g_h1 : g_h0) + (size_t)(row0 + r) * HE + k0g + c * 8;
                cp16(sbase + st * STG + t * OATILE + (r * OAP + c * 8) * 2, g);
            } else {
                int j = i - 1024;
                int t = j >> 10, rc = j & 1023, r = rc >> 3, c = rc & 7;
                const __half* g = (t ? g_w1 : g_w0) + (size_t)r * HE + k0g + c * 8;
                cp16(sbase + st * STG + 2 * OATILE + t * OBTILE + (r * OAP + c * 8) * 2, g);
            }
        }
        cp_commit();
    };

    float acc[2][4][4];
    #pragma unroll
    for (int mt = 0; mt < 2; ++mt)
        #pragma unroll
        for (int nt = 0; nt < 4; ++nt)
            #pragma unroll
            for (int i = 0; i < 4; ++i) acc[mt][nt][i] = 0.f;

    load_chunk(0, 0);
    for (int ck = 0; ck < 18; ++ck) {
        if (ck + 1 < 18) load_chunk((ck + 1) & 1, ck + 1);
        if (ck + 1 < 18) cp_wait<1>(); else cp_wait<0>();
        __syncthreads();

        const u32 st = sbase + (ck & 1) * STG;
        const int PA[3] = {0, 0, 1};
        const int PB[3] = {0, 1, 0};
        #pragma unroll
        for (int l = 0; l < 3; ++l) {
            u32 abase = st + PA[l] * OATILE;
            u32 bbase = st + 2 * OATILE + PB[l] * OBTILE;
            #pragma unroll
            for (int k = 0; k < 4; ++k) {
                const int k0 = k * 16;
                u32 bfrag[4][2];
                u32 brow = bbase + ((wc * 32 + (l15 & 7)) * OAP + k0 + ((l15 >> 3) * 8)) * 2;
                #pragma unroll
                for (int nt = 0; nt < 4; ++nt)
                    ldmx2(bfrag[nt][0], bfrag[nt][1], brow + (nt * 8 * OAP) * 2);
                u32 arow = abase + ((wr * 32 + l15) * OAP + k0 + ((lane >> 4) * 8)) * 2;
                #pragma unroll
                for (int mt = 0; mt < 2; ++mt) {
                    u32 a0, a1, a2, a3;
                    ldmx4(a0, a1, a2, a3, arow + (mt * 16 * OAP) * 2);
                    #pragma unroll
                    for (int nt = 0; nt < 4; ++nt)
                        mma16816(acc[mt][nt], a0, a1, a2, a3, bfrag[nt][0], bfrag[nt][1]);
                }
            }
        }
        __syncthreads();
    }

    float* stage = (float*)sm;
    {
        int row = wr * 32 + (lane >> 2);
        int col = wc * 32 + (lane & 3) * 2;
        #pragma unroll
        for (int mt = 0; mt < 2; ++mt)
            #pragma unroll
            for (int nt = 0; nt < 4; ++nt) {
                float* c = acc[mt][nt];
                int rr = row + mt * 16, cc = col + nt * 8;
                stage[rr * 129 + cc]           = c[0];
                stage[rr * 129 + cc + 1]       = c[1];
                stage[(rr + 8) * 129 + cc]     = c[2];
                stage[(rr + 8) * 129 + cc + 1] = c[3];
            }
    }
    __syncthreads();
    for (int idx = tid; idx < 128 * 64; idx += 256) {
        int e = idx >> 6, rr = idx & 63;
        int rg = row0 + rr;
        if (rg < Bb * Ss) {
            int b = rg / Ss, s = rg % Ss;
            out[((size_t)b * Ee + e) * Ss + s] = stage[rr * 129 + e] + bias[e];
        }
    }
}

// =================================================================
extern "C" void kernel_launch(void* const* d_in, const int* in_sizes, int n_in,
                              void* d_out, int out_size)
{
    const float* x    = (const float*)d_in[0];
    const float* Qw   = (const float*)d_in[1];
    const float* Kw   = (const float*)d_in[2];
    const float* Vw   = (const float*)d_in[3];
    const float* Wm   = (const float*)d_in[4];
    const float* bias = (const float*)d_in[5];

    float* out   = (float*)d_out;                    // [B,E,S]
    float* atten = out + (size_t)Bb * Ee * Ss;       // [B,H,S,S]

    const int smemP = 2 * (2 * CTILE + 2 * VTILE32); // 75,776
    const int smemS = 2 * 4 * CTILE;                 // 81,920
    const int smemA = 128 * 130 * 4;                 // 66,560 (stage > 2*STG=55,296)
    const int smemO = 2 * (2 * OATILE + 2 * OBTILE); // 110,592

    cudaFuncSetAttribute(proj_kernel,    cudaFuncAttributeMaxDynamicSharedMemorySize, smemP);
    cudaFuncSetAttribute(scores_kernel,  cudaFuncAttributeMaxDynamicSharedMemorySize, smemS);
    cudaFuncSetAttribute(av_kernel,      cudaFuncAttributeMaxDynamicSharedMemorySize, smemA);
    cudaFuncSetAttribute(outproj_kernel, cudaFuncAttributeMaxDynamicSharedMemorySize, smemO);

    wprep_kernel<<<576, 256>>>(Wm);
    qkvprep_kernel<<<1728, 256>>>(Qw, Kw, Vw);
    xprep_kernel<<<dim3(17, Bb), 256>>>(x);
    proj_kernel<<<dim3(9, Bb, 27), 256, smemP>>>();
    scores_kernel<<<dim3(81, Bb * Hh), 256, smemS>>>(atten);
    softmax_kernel<<<Bb * Hh * Ss, 128>>>(atten);
    av_kernel<<<dim3(9, Bb * Hh), 256, smemA>>>();
    outproj_kernel<<<130, 256, smemO>>>(bias, out);
}

// round 11
// speedup vs baseline: 3.3140x; 1.1450x over previous
#include <cuda_runtime.h>
#include <cuda_fp16.h>

#define Bb 8
#define Hh 9
#define Ee 128
#define Ss 1025
#define SPAD 1152   // padded sequence (rows/cols >=1025 stay zero-initialized)
#define HE 1152
#define ROWP 8320   // padded out-proj row count (65*128)
#define CP 40       // fp16 pitch for [128 x 32] k-chunk tiles
#define CTILE 10240 // 128*40*2 bytes
#define VP 136      // fp16 pitch for [32 x 128] B-trans chunk tiles
#define VTILE32 8704 // 32*136*2 bytes
#define OAP 72      // outproj pitch for k64 tiles
#define OATILE 9216  // 64*72*2
#define OBTILE 18432 // 128*72*2

typedef unsigned long long ull;
typedef unsigned int u32;

// ---------------- scratch (zero-initialized BSS; padding never written) ------
__device__ __half g_x0[Bb * SPAD * 128], g_x1[Bb * SPAD * 128];
__device__ __half g_wq0[Hh * Ee * Ee], g_wq1[Hh * Ee * Ee];
__device__ __half g_wk0[Hh * Ee * Ee], g_wk1[Hh * Ee * Ee];
__device__ __half g_wv0[Hh * Ee * Ee], g_wv1[Hh * Ee * Ee];
__device__ __half g_q0[72 * SPAD * 128], g_q1[72 * SPAD * 128];
__device__ __half g_k0[72 * SPAD * 128], g_k1[72 * SPAD * 128];
__device__ __half g_v0[72 * SPAD * 128];
__device__ __half g_p0[(size_t)72 * SPAD * SPAD];
__device__ __half g_h0[ROWP * HE];
__device__ __half g_w0[Ee * HE];

// ---------------- async copy / mma helpers ----------------
__device__ __forceinline__ u32 s2u(const void* p) {
    u32 a;
    asm("{ .reg .u64 t; cvta.to.shared.u64 t, %1; cvt.u32.u64 %0, t; }" : "=r"(a) : "l"(p));
    return a;
}
__device__ __forceinline__ void cp16(u32 smem, const void* g) {
    asm volatile("cp.async.cg.shared.global [%0], [%1], 16;" :: "r"(smem), "l"(g));
}
__device__ __forceinline__ void cp_commit() { asm volatile("cp.async.commit_group;" ::: "memory"); }
template <int N> __device__ __forceinline__ void cp_wait() {
    asm volatile("cp.async.wait_group %0;" :: "n"(N) : "memory");
}
__device__ __forceinline__ void ldmx4(u32& a0, u32& a1, u32& a2, u32& a3, u32 addr) {
    asm volatile("ldmatrix.sync.aligned.m8n8.x4.shared.b16 {%0,%1,%2,%3}, [%4];"
                 : "=r"(a0), "=r"(a1), "=r"(a2), "=r"(a3) : "r"(addr));
}
__device__ __forceinline__ void ldmx2(u32& b0, u32& b1, u32 addr) {
    asm volatile("ldmatrix.sync.aligned.m8n8.x2.shared.b16 {%0,%1}, [%2];"
                 : "=r"(b0), "=r"(b1) : "r"(addr));
}
__device__ __forceinline__ void ldmx2t(u32& b0, u32& b1, u32 addr) {
    asm volatile("ldmatrix.sync.aligned.m8n8.x2.trans.shared.b16 {%0,%1}, [%2];"
                 : "=r"(b0), "=r"(b1) : "r"(addr));
}
__device__ __forceinline__ void mma16816(float* c, u32 a0, u32 a1, u32 a2, u32 a3,
                                         u32 b0, u32 b1) {
    asm volatile("mma.sync.aligned.m16n8k16.row.col.f32.f16.f16.f32 "
                 "{%0,%1,%2,%3}, {%4,%5,%6,%7}, {%8,%9}, {%0,%1,%2,%3};"
                 : "+f"(c[0]), "+f"(c[1]), "+f"(c[2]), "+f"(c[3])
                 : "r"(a0), "r"(a1), "r"(a2), "r"(a3), "r"(b0), "r"(b1));
}
__device__ __forceinline__ void hsplit2(float x, __half& a, __half& b) {
    a = __float2half_rn(x);
    b = __float2half_rn(x - __half2float(a));
}

// =================================================================
// Kernel 0a: W -> fp16 (single level)
// =================================================================
__global__ __launch_bounds__(256) void wprep_kernel(const float* __restrict__ Wm)
{
    int idx = blockIdx.x * 256 + threadIdx.x;
    if (idx < Ee * HE)
        g_w0[idx] = __float2half_rn(Wm[idx]);
}

// =================================================================
// Kernel 0b: split Q/K/V weight matrices into fp16 levels (natural [h][e][f])
// =================================================================
__global__ __launch_bounds__(256) void qkvprep_kernel(
    const float* __restrict__ Qw, const float* __restrict__ Kw,
    const float* __restrict__ Vw)
{
    int idx = blockIdx.x * 256 + threadIdx.x;
    const int N = Hh * Ee * Ee;
    if (idx < 3 * N) {
        int z = idx / N, j = idx % N;
        const float* src = (z == 0) ? Qw : (z == 1) ? Kw : Vw;
        __half* d0 = (z == 0) ? g_wq0 : (z == 1) ? g_wk0 : g_wv0;
        __half* d1 = (z == 0) ? g_wq1 : (z == 1) ? g_wk1 : g_wv1;
        __half a, b;
        hsplit2(src[j], a, b);
        d0[j] = a;
        d1[j] = b;
    }
}

// =================================================================
// Kernel 0c: transpose x [B,E,S] -> xt splits [b][s][e] fp16 x2
// =================================================================
__global__ __launch_bounds__(256) void xprep_kernel(const float* __restrict__ x)
{
    __shared__ float ts[128 * 65];
    const int tid = threadIdx.x;
    const int s0 = blockIdx.x * 64;
    const int b = blockIdx.y;

    #pragma unroll
    for (int it = 0; it < 32; ++it) {
        int idx = tid + it * 256;
        int e = idx >> 6, sl = idx & 63;
        int s = s0 + sl;
        ts[e * 65 + sl] = (s < Ss) ? x[((size_t)b * Ee + e) * Ss + s] : 0.f;
    }
    __syncthreads();
    #pragma unroll
    for (int it = 0; it < 32; ++it) {
        int idx = tid + it * 256;
        int sl = idx >> 7, e = idx & 127;
        int s = s0 + sl;
        if (s < Ss) {
            __half a, bb;
            hsplit2(ts[e * 65 + sl], a, bb);
            size_t o = ((size_t)b * SPAD + s) * 128 + e;
            g_x0[o] = a;
            g_x1[o] = bb;
        }
    }
}

// =================================================================
// Kernel 1: projections via fp16 HMMA (3 products), 4 k32 chunks.
// Grid (9, 8, 27). 2 CTAs/SM. q/k get split2 output; v single fp16.
// =================================================================
__global__ __launch_bounds__(256, 2) void proj_kernel()
{
    extern __shared__ __align__(16) unsigned char sm[];
    const u32 sbase = s2u(sm);
    const int tid = threadIdx.x, wid = tid >> 5, lane = tid & 31;
    const int m0 = blockIdx.x * 128;
    const int b = blockIdx.y;
    const int zt = blockIdx.z % 3, h = blockIdx.z / 3;
    const int wr = wid >> 2, wc = wid & 3;
    const int l15 = lane & 15;
    const int STG = 2 * CTILE + 2 * VTILE32;   // 37,888

    const __half* w0 = (zt == 0) ? g_wq0 : (zt == 1) ? g_wk0 : g_wv0;
    const __half* w1 = (zt == 0) ? g_wq1 : (zt == 1) ? g_wk1 : g_wv1;

    auto load_chunk = [&](int st, int ck) {
        const int e0 = ck * 32;
        for (int i = tid; i < 2048; i += 256) {
            if (i < 1024) {
                int t = i >> 9, rc = i & 511, r = rc >> 2, c = rc & 3;
                const __half* g = (t ? g_x1 : g_x0) +
                    ((size_t)b * SPAD + m0 + r) * 128 + e0 + c * 8;
                cp16(sbase + st * STG + t * CTILE + (r * CP + c * 8) * 2, g);
            } else {
                int j = i - 1024;
                int t = j >> 9, rc = j & 511, r = rc >> 4, c = rc & 15;
                const __half* g = (t ? w1 : w0) + ((size_t)h * 128 + e0 + r) * 128 + c * 8;
                cp16(sbase + st * STG + 2 * CTILE + t * VTILE32 + (r * VP + c * 8) * 2, g);
            }
        }
        cp_commit();
    };

    float acc[4][4][4];
    #pragma unroll
    for (int mt = 0; mt < 4; ++mt)
        #pragma unroll
        for (int nt = 0; nt < 4; ++nt)
            #pragma unroll
            for (int i = 0; i < 4; ++i) acc[mt][nt][i] = 0.f;

    load_chunk(0, 0);
    for (int ck = 0; ck < 4; ++ck) {
        if (ck + 1 < 4) load_chunk((ck + 1) & 1, ck + 1);
        if (ck + 1 < 4) cp_wait<1>(); else cp_wait<0>();
        __syncthreads();

        const u32 st = sbase + (ck & 1) * STG;
        const int PA[3] = {0, 0, 1};
        const int PB[3] = {0, 1, 0};
        #pragma unroll
        for (int l = 0; l < 3; ++l) {
            u32 abase = st + PA[l] * CTILE;
            u32 vbase = st + 2 * CTILE + PB[l] * VTILE32;
            #pragma unroll
            for (int k = 0; k < 2; ++k) {
                const int k0 = k * 16;
                u32 bfrag[4][2];
                u32 brow = vbase + ((k0 + l15) * VP) * 2;
                #pragma unroll
                for (int nt = 0; nt < 4; ++nt)
                    ldmx2t(bfrag[nt][0], bfrag[nt][1], brow + (wc * 32 + nt * 8) * 2);
                u32 arow = abase + ((wr * 64 + l15) * CP + k0 + ((lane >> 4) * 8)) * 2;
                #pragma unroll
                for (int mt = 0; mt < 4; ++mt) {
                    u32 a0, a1, a2, a3;
                    ldmx4(a0, a1, a2, a3, arow + (mt * 16 * CP) * 2);
                    #pragma unroll
                    for (int nt = 0; nt < 4; ++nt)
                        mma16816(acc[mt][nt], a0, a1, a2, a3, bfrag[nt][0], bfrag[nt][1]);
                }
            }
        }
        __syncthreads();
    }

    // epilogue: regs -> stage -> q/k fp16 splits (v: single level)
    float* stage = (float*)sm;   // [128][130]
    {
        int row = wr * 64 + (lane >> 2);
        int col = wc * 32 + (lane & 3) * 2;
        #pragma unroll
        for (int mt = 0; mt < 4; ++mt)
            #pragma unroll
            for (int nt = 0; nt < 4; ++nt) {
                float* c = acc[mt][nt];
                int rr = row + mt * 16, cc = col + nt * 8;
                *(float2*)&stage[rr * 130 + cc]       = make_float2(c[0], c[1]);
                *(float2*)&stage[(rr + 8) * 130 + cc] = make_float2(c[2], c[3]);
            }
    }
    __syncthreads();
    __half* d0 = (zt == 0) ? g_q0 : (zt == 1) ? g_k0 : g_v0;
    __half* d1 = (zt == 0) ? g_q1 : g_k1;   // valid only when zt < 2
    const int bh = b * Hh + h;
    for (int idx = tid; idx < 128 * 16; idx += 256) {
        int rr = idx >> 4, c8 = (idx & 15) * 8;
        int s = m0 + rr;
        if (s < Ss) {
            size_t base = ((size_t)bh * SPAD + s) * 128 + c8;
            union { uint4 u; __half hh[8]; } h0, h1;
            if (zt < 2) {
                #pragma unroll
                for (int c = 0; c < 8; ++c)
                    hsplit2(stage[rr * 130 + c8 + c], h0.hh[c], h1.hh[c]);
                *(uint4*)&d0[base] = h0.u;
                *(uint4*)&d1[base] = h1.u;
            } else {
                #pragma unroll
                for (int c = 0; c < 8; ++c)
                    h0.hh[c] = __float2half_rn(stage[rr * 130 + c8 + c]);
                *(uint4*)&d0[base] = h0.u;
            }
        }
    }
}

// =================================================================
// Kernel 2: scores. fp16 GEMM, 2-way split (3 products), 4 k32 chunks.
// Grid (81, 72). 2 CTAs/SM.
// =================================================================
__global__ __launch_bounds__(256, 2) void scores_kernel(float* __restrict__ atten)
{
    extern __shared__ __align__(16) unsigned char sm[];
    const u32 sbase = s2u(sm);
    const int tid = threadIdx.x, wid = tid >> 5, lane = tid & 31;
    const int m0 = (blockIdx.x / 9) * 128, n0r = (blockIdx.x % 9) * 128;
    const int bh = blockIdx.y;
    const int wr = wid >> 2, wc = wid & 3;
    const int l15 = lane & 15;
    const int STG = 4 * CTILE;

    auto load_chunk = [&](int st, int kc) {
        const int e0 = kc * 32;
        for (int i = tid; i < 2048; i += 256) {
            int t = i >> 9, rc = i & 511, r = rc >> 2, c = rc & 3;
            const __half* src = (t == 0) ? g_q0 : (t == 1) ? g_q1 : (t == 2) ? g_k0 : g_k1;
            int row0 = (t < 2) ? m0 : n0r;
            cp16(sbase + st * STG + t * CTILE + (r * CP + c * 8) * 2,
                 src + ((size_t)bh * SPAD + row0 + r) * 128 + e0 + c * 8);
        }
        cp_commit();
    };

    float acc[4][4][4];
    #pragma unroll
    for (int mt = 0; mt < 4; ++mt)
        #pragma unroll
        for (int nt = 0; nt < 4; ++nt)
            #pragma unroll
            for (int i = 0; i < 4; ++i) acc[mt][nt][i] = 0.f;

    load_chunk(0, 0);
    for (int kc = 0; kc < 4; ++kc) {
        if (kc + 1 < 4) load_chunk((kc + 1) & 1, kc + 1);
        if (kc + 1 < 4) cp_wait<1>(); else cp_wait<0>();
        __syncthreads();
        const u32 st = sbase + (kc & 1) * STG;
        const int PA[3] = {0, 0, 1};
        const int PB[3] = {0, 1, 0};
        #pragma unroll
        for (int l = 0; l < 3; ++l) {
            u32 abase = st + PA[l] * CTILE;
            u32 bbase = st + (2 + PB[l]) * CTILE;
            #pragma unroll
            for (int k = 0; k < 2; ++k) {
                const int k0 = k * 16;
                u32 bfrag[4][2];
                u32 brow = bbase + ((wc * 32 + (l15 & 7)) * CP + k0 + ((l15 >> 3) * 8)) * 2;
                #pragma unroll
                for (int nt = 0; nt < 4; ++nt)
                    ldmx2(bfrag[nt][0], bfrag[nt][1], brow + (nt * 8 * CP) * 2);
                u32 arow = abase + ((wr * 64 + l15) * CP + k0 + ((lane >> 4) * 8)) * 2;
                #pragma unroll
                for (int mt = 0; mt < 4; ++mt) {
                    u32 a0, a1, a2, a3;
                    ldmx4(a0, a1, a2, a3, arow + (mt * 16 * CP) * 2);
                    #pragma unroll
                    for (int nt = 0; nt < 4; ++nt)
                        mma16816(acc[mt][nt], a0, a1, a2, a3, bfrag[nt][0], bfrag[nt][1]);
                }
            }
        }
        __syncthreads();
    }

    float* stage = (float*)sm;   // [128][130]
    {
        int row = wr * 64 + (lane >> 2);
        int col = wc * 32 + (lane & 3) * 2;
        #pragma unroll
        for (int mt = 0; mt < 4; ++mt)
            #pragma unroll
            for (int nt = 0; nt < 4; ++nt) {
                float* c = acc[mt][nt];
                int rr = row + mt * 16, cc = col + nt * 8;
                *(float2*)&stage[rr * 130 + cc]       = make_float2(c[0], c[1]);
                *(float2*)&stage[(rr + 8) * 130 + cc] = make_float2(c[2], c[3]);
            }
    }
    __syncthreads();
    const float scl = 0.08838834764831845f;  // 1/sqrt(128)
    for (int idx = tid; idx < 128 * 128; idx += 256) {
        int rr = idx >> 7, c = idx & 127;
        int s = m0 + rr, t = n0r + c;
        if (s < Ss && t < Ss)
            atten[((size_t)bh * Ss + s) * Ss + t] = stage[rr * 130 + c] * scl;
    }
}

// =================================================================
// Kernel 3: softmax per row; writes fp32 atten AND single fp16 P0.
// =================================================================
__global__ __launch_bounds__(128) void softmax_kernel(float* __restrict__ atten)
{
    __shared__ float buf[Ss];
    __shared__ float redm[4], reds[4];
    const int tid = threadIdx.x, wid = tid >> 5, lid = tid & 31;
    const int row = blockIdx.x;
    const int bh = row / Ss, s = row % Ss;
    float* p = atten + (size_t)row * Ss;

    float m = -3.0e38f;
    for (int c = tid; c < Ss; c += 128) { float v = p[c]; buf[c] = v; m = fmaxf(m, v); }
    #pragma unroll
    for (int o = 16; o; o >>= 1) m = fmaxf(m, __shfl_xor_sync(0xffffffffu, m, o));
    if (lid == 0) redm[wid] = m;
    __syncthreads();
    m = fmaxf(fmaxf(redm[0], redm[1]), fmaxf(redm[2], redm[3]));

    float sum = 0.f;
    for (int c = tid; c < Ss; c += 128) { float e = __expf(buf[c] - m); buf[c] = e; sum += e; }
    #pragma unroll
    for (int o = 16; o; o >>= 1) sum += __shfl_xor_sync(0xffffffffu, sum, o);
    if (lid == 0) reds[wid] = sum;
    __syncthreads();
    float inv = 1.f / (reds[0] + reds[1] + reds[2] + reds[3]);

    __half* prow = g_p0 + ((size_t)bh * SPAD + s) * SPAD;
    for (int c2 = tid; c2 * 2 < Ss; c2 += 128) {
        int c = c2 * 2;
        float pr0 = buf[c] * inv;
        p[c] = pr0;
        if (c + 1 < Ss) {
            float pr1 = buf[c + 1] * inv;
            p[c + 1] = pr1;
            *(__half2*)&prow[c] = __floats2half2_rn(pr0, pr1);
        } else {
            prow[c] = __float2half_rn(pr0);
        }
    }
}

// =================================================================
// Kernel 4: AV. fp16 P0 x V0 (1 product), 36 k32 chunks.
// Grid (9, 72). 2 CTAs/SM. Emits ho single fp16.
// smem = max(2*STG=37,888, stage 128*130*4=66,560) = 66,560
// =================================================================
__global__ __launch_bounds__(256, 2) void av_kernel()
{
    extern __shared__ __align__(16) unsigned char sm[];
    const u32 sbase = s2u(sm);
    const int tid = threadIdx.x, wid = tid >> 5, lane = tid & 31;
    const int m0 = blockIdx.x * 128;
    const int bh = blockIdx.y;
    const int b = bh / Hh, h = bh % Hh;
    const int wr = wid >> 2, wc = wid & 3;
    const int l15 = lane & 15;
    const int STG = CTILE + VTILE32;   // 18,944

    auto load_chunk = [&](int st, int ck) {
        const int t0 = ck * 32;
        for (int i = tid; i < 1024; i += 256) {
            if (i < 512) {
                int r = i >> 2, c = i & 3;
                const __half* g = g_p0 + ((size_t)bh * SPAD + m0 + r) * SPAD + t0 + c * 8;
                cp16(sbase + st * STG + (r * CP + c * 8) * 2, g);
            } else {
                int j = i - 512;
                int r = j >> 4, c = j & 15;
                const __half* g = g_v0 + ((size_t)bh * SPAD + t0 + r) * 128 + c * 8;
                cp16(sbase + st * STG + CTILE + (r * VP + c * 8) * 2, g);
            }
        }
        cp_commit();
    };

    float acc[4][4][4];
    #pragma unroll
    for (int mt = 0; mt < 4; ++mt)
        #pragma unroll
        for (int nt = 0; nt < 4; ++nt)
            #pragma unroll
            for (int i = 0; i < 4; ++i) acc[mt][nt][i] = 0.f;

    load_chunk(0, 0);
    for (int ck = 0; ck < 36; ++ck) {
        if (ck + 1 < 36) load_chunk((ck + 1) & 1, ck + 1);
        if (ck + 1 < 36) cp_wait<1>(); else cp_wait<0>();
        __syncthreads();

        const u32 st = sbase + (ck & 1) * STG;
        const u32 vbase = st + CTILE;
        #pragma unroll
        for (int k = 0; k < 2; ++k) {
            const int k0 = k * 16;
            u32 bfrag[4][2];
            u32 brow = vbase + ((k0 + l15) * VP) * 2;
            #pragma unroll
            for (int nt = 0; nt < 4; ++nt)
                ldmx2t(bfrag[nt][0], bfrag[nt][1], brow + (wc * 32 + nt * 8) * 2);
            u32 arow = st + ((wr * 64 + l15) * CP + k0 + ((lane >> 4) * 8)) * 2;
            #pragma unroll
            for (int mt = 0; mt < 4; ++mt) {
                u32 a0, a1, a2, a3;
                ldmx4(a0, a1, a2, a3, arow + (mt * 16 * CP) * 2);
                #pragma unroll
                for (int nt = 0; nt < 4; ++nt)
                    mma16816(acc[mt][nt], a0, a1, a2, a3, bfrag[nt][0], bfrag[nt][1]);
            }
        }
        __syncthreads();
    }

    float* stage = (float*)sm;   // [128][130] = 66,560 B
    {
        int row = wr * 64 + (lane >> 2);
        int col = wc * 32 + (lane & 3) * 2;
        #pragma unroll
        for (int mt = 0; mt < 4; ++mt)
            #pragma unroll
            for (int nt = 0; nt < 4; ++nt) {
                float* c = acc[mt][nt];
                int rr = row + mt * 16, cc = col + nt * 8;
                *(float2*)&stage[rr * 130 + cc]       = make_float2(c[0], c[1]);
                *(float2*)&stage[(rr + 8) * 130 + cc] = make_float2(c[2], c[3]);
            }
    }
    __syncthreads();
    for (int idx = tid; idx < 128 * 16; idx += 256) {
        int rr = idx >> 4, c8 = (idx & 15) * 8;
        int s = m0 + rr;
        if (s < Ss) {
            union { uint4 u; __half hh[8]; } h0;
            #pragma unroll
            for (int c = 0; c < 8; ++c)
                h0.hh[c] = __float2half_rn(stage[rr * 130 + c8 + c]);
            *(uint4*)&g_h0[((size_t)b * Ss + s) * HE + h * Ee + c8] = h0.u;
        }
    }
}

// =================================================================
// Kernel 5: outproj via fp16 HMMA (1 product), 18 k64 chunks. 2 CTAs/SM.
// =================================================================
__global__ __launch_bounds__(256, 2) void outproj_kernel(
    const float* __restrict__ bias, float* __restrict__ out)
{
    extern __shared__ __align__(16) unsigned char sm[];
    const u32 sbase = s2u(sm);
    const int tid = threadIdx.x, wid = tid >> 5, lane = tid & 31;
    const int row0 = blockIdx.x * 64;
    const int wr = wid >> 2, wc = wid & 3;
    const int l15 = lane & 15;
    const int STG = OATILE + OBTILE;   // 27,648

    auto load_chunk = [&](int st, int ck) {
        const int k0g = ck * 64;
        for (int i = tid; i < 1536; i += 256) {
            if (i < 512) {
                int r = i >> 3, c = i & 7;
                const __half* g = g_h0 + (size_t)(row0 + r) * HE + k0g + c * 8;
                cp16(sbase + st * STG + (r * OAP + c * 8) * 2, g);
            } else {
                int j = i - 512;
                int r = j >> 3, c = j & 7;
                const __half* g = g_w0 + (size_t)r * HE + k0g + c * 8;
                cp16(sbase + st * STG + OATILE + (r * OAP + c * 8) * 2, g);
            }
        }
        cp_commit();
    };

    float acc[2][4][4];
    #pragma unroll
    for (int mt = 0; mt < 2; ++mt)
        #pragma unroll
        for (int nt = 0; nt < 4; ++nt)
            #pragma unroll
            for (int i = 0; i < 4; ++i) acc[mt][nt][i] = 0.f;

    load_chunk(0, 0);
    for (int ck = 0; ck < 18; ++ck) {
        if (ck + 1 < 18) load_chunk((ck + 1) & 1, ck + 1);
        if (ck + 1 < 18) cp_wait<1>(); else cp_wait<0>();
        __syncthreads();

        const u32 st = sbase + (ck & 1) * STG;
        const u32 bbase = st + OATILE;
        #pragma unroll
        for (int k = 0; k < 4; ++k) {
            const int k0 = k * 16;
            u32 bfrag[4][2];
            u32 brow = bbase + ((wc * 32 + (l15 & 7)) * OAP + k0 + ((l15 >> 3) * 8)) * 2;
            #pragma unroll
            for (int nt = 0; nt < 4; ++nt)
                ldmx2(bfrag[nt][0], bfrag[nt][1], brow + (nt * 8 * OAP) * 2);
            u32 arow = st + ((wr * 32 + l15) * OAP + k0 + ((lane >> 4) * 8)) * 2;
            #pragma unroll
            for (int mt = 0; mt < 2; ++mt) {
                u32 a0, a1, a2, a3;
                ldmx4(a0, a1, a2, a3, arow + (mt * 16 * OAP) * 2);
                #pragma unroll
                for (int nt = 0; nt < 4; ++nt)
                    mma16816(acc[mt][nt], a0, a1, a2, a3, bfrag[nt][0], bfrag[nt][1]);
            }
        }
        __syncthreads();
    }

    float* stage = (float*)sm;   // [64][129] = 33,024 B
    {
        int row = wr * 32 + (lane >> 2);
        int col = wc * 32 + (lane & 3) * 2;
        #pragma unroll
        for (int mt = 0; mt < 2; ++mt)
            #pragma unroll
            for (int nt = 0; nt < 4; ++nt) {
                float* c = acc[mt][nt];
                int rr = row + mt * 16, cc = col + nt * 8;
                stage[rr * 129 + cc]           = c[0];
                stage[rr * 129 + cc + 1]       = c[1];
                stage[(rr + 8) * 129 + cc]     = c[2];
                stage[(rr + 8) * 129 + cc + 1] = c[3];
            }
    }
    __syncthreads();
    for (int idx = tid; idx < 128 * 64; idx += 256) {
        int e = idx >> 6, rr = idx & 63;
        int rg = row0 + rr;
        if (rg < Bb * Ss) {
            int b = rg / Ss, s = rg % Ss;
            out[((size_t)b * Ee + e) * Ss + s] = stage[rr * 129 + e] + bias[e];
        }
    }
}

// =================================================================
extern "C" void kernel_launch(void* const* d_in, const int* in_sizes, int n_in,
                              void* d_out, int out_size)
{
    const float* x    = (const float*)d_in[0];
    const float* Qw   = (const float*)d_in[1];
    const float* Kw   = (const float*)d_in[2];
    const float* Vw   = (const float*)d_in[3];
    const float* Wm   = (const float*)d_in[4];
    const float* bias = (const float*)d_in[5];

    float* out   = (float*)d_out;                    // [B,E,S]
    float* atten = out + (size_t)Bb * Ee * Ss;       // [B,H,S,S]

    const int smemP = 2 * (2 * CTILE + 2 * VTILE32); // 75,776
    const int smemS = 2 * 4 * CTILE;                 // 81,920
    const int smemA = 128 * 130 * 4;                 // 66,560 (stage > 2*STG=37,888)
    const int smemO = 2 * (OATILE + OBTILE);         // 55,296 (> stage 33,024)

    cudaFuncSetAttribute(proj_kernel,    cudaFuncAttributeMaxDynamicSharedMemorySize, smemP);
    cudaFuncSetAttribute(scores_kernel,  cudaFuncAttributeMaxDynamicSharedMemorySize, smemS);
    cudaFuncSetAttribute(av_kernel,      cudaFuncAttributeMaxDynamicSharedMemorySize, smemA);
    cudaFuncSetAttribute(outproj_kernel, cudaFuncAttributeMaxDynamicSharedMemorySize, smemO);

    wprep_kernel<<<576, 256>>>(Wm);
    qkvprep_kernel<<<1728, 256>>>(Qw, Kw, Vw);
    xprep_kernel<<<dim3(17, Bb), 256>>>(x);
    proj_kernel<<<dim3(9, Bb, 27), 256, smemP>>>();
    scores_kernel<<<dim3(81, Bb * Hh), 256, smemS>>>(atten);
    softmax_kernel<<<Bb * Hh * Ss, 128>>>(atten);
    av_kernel<<<dim3(9, Bb * Hh), 256, smemA>>>();
    outproj_kernel<<<130, 256, smemO>>>(bias, out);
}